// round 8
// baseline (speedup 1.0000x reference)
#include <cuda_runtime.h>
#include <cuda_bf16.h>
#include <cstdint>

#define BSZ 32
#define CNT 128
#define Wd  2048
#define Pd  1024
#define Ed  8
#define Kc  25
#define Ld  2
#define ROWS (BSZ*CNT)   // 4096

typedef __nv_bfloat16 bf16;

// ---------------- scratch ----------------
__device__ float g_x[ROWS*Wd];
__device__ bf16  g_ch[ROWS*Wd];
__device__ bf16  g_cm[ROWS*Wd];
__device__ float g_qkv[3*ROWS*Pd];
__device__ bf16  g_ph[ROWS*Pd];
__device__ bf16  g_pm[ROWS*Pd];
__device__ bf16  g_wqkvh[3*Ld*Pd*Wd];
__device__ bf16  g_wqkvm[3*Ld*Pd*Wd];
__device__ bf16  g_woh[Ld*Wd*Pd];
__device__ bf16  g_wom[Ld*Wd*Pd];
__device__ float g_bqkv[3*Ld*Pd];
__device__ float g_wavg[Ld*Kc];
__device__ float g_bavg[Ld];

// ---------------- helpers ----------------
__device__ __forceinline__ uint32_t smem_u32(const void* p) {
    uint32_t a;
    asm("{ .reg .u64 t; cvta.to.shared.u64 t, %1; cvt.u32.u64 %0, t; }" : "=r"(a) : "l"(p));
    return a;
}
__device__ __forceinline__ void cp16(uint32_t dst, const void* src) {
    asm volatile("cp.async.cg.shared.global [%0], [%1], 16;" :: "r"(dst), "l"(src));
}
__device__ __forceinline__ void split2(float x, bf16& h, bf16& m) {
    h = __float2bfloat16(x);
    m = __float2bfloat16(x - __bfloat162float(h));
}
__device__ __forceinline__ uint32_t pack2(bf16 a, bf16 b) {
    return (uint32_t)__bfloat16_as_ushort(a) | ((uint32_t)__bfloat16_as_ushort(b) << 16);
}

// ---------------- weight split fp32 -> 2x bf16 ----------------
__global__ void split2_kernel(const float* __restrict__ src, bf16* __restrict__ h,
                              bf16* __restrict__ m, int n8) {
    int i = blockIdx.x * blockDim.x + threadIdx.x;
    int stride = gridDim.x * blockDim.x;
    for (; i < n8; i += stride) {
        float4 v0 = ((const float4*)src)[2 * i];
        float4 v1 = ((const float4*)src)[2 * i + 1];
        float v[8] = {v0.x, v0.y, v0.z, v0.w, v1.x, v1.y, v1.z, v1.w};
        bf16 hh[8], mm_[8];
        #pragma unroll
        for (int e = 0; e < 8; e++) split2(v[e], hh[e], mm_[e]);
        uint4 u;
        u.x = pack2(hh[0], hh[1]); u.y = pack2(hh[2], hh[3]);
        u.z = pack2(hh[4], hh[5]); u.w = pack2(hh[6], hh[7]);
        ((uint4*)h)[i] = u;
        u.x = pack2(mm_[0], mm_[1]); u.y = pack2(mm_[2], mm_[3]);
        u.z = pack2(mm_[4], mm_[5]); u.w = pack2(mm_[6], mm_[7]);
        ((uint4*)m)[i] = u;
    }
}

// ---------------- avg conv weights ----------------
__global__ void avg_conv_kernel(const float* __restrict__ cw, const float* __restrict__ cb,
                                float* __restrict__ wavg, float* __restrict__ bavg) {
    int idx = threadIdx.x;
    if (idx < Ld * Kc) {
        int l = idx / Kc, kk = idx % Kc;
        float s = 0.f;
        #pragma unroll
        for (int e = 0; e < Ed; e++) s += cw[(l * Ed + e) * Kc + kk];
        wavg[idx] = s * (1.0f / Ed);
    }
    if (idx < Ld) {
        float s = 0.f;
        #pragma unroll
        for (int e = 0; e < Ed; e++) s += cb[idx * Ed + e];
        bavg[idx] = s * (1.0f / Ed);
    }
}

// ---------------- 1D conv, writes 2x bf16 ----------------
__global__ __launch_bounds__(256) void conv_row_kernel(
    const float* __restrict__ X, bf16* __restrict__ Yh, bf16* __restrict__ Ym,
    const float* __restrict__ wavg, const float* __restrict__ bavg)
{
    __shared__ float sx[Wd + Kc - 1];
    __shared__ float wsh[Kc];
    const int row = blockIdx.x;
    const int tid = threadIdx.x;
    const float* xr = X + (size_t)row * Wd;

    for (int i = tid; i < Wd + Kc - 1; i += 256) {
        int src = i - (Kc / 2);
        sx[i] = (src >= 0 && src < Wd) ? xr[src] : 0.0f;
    }
    if (tid < Kc) wsh[tid] = wavg[tid];
    __syncthreads();

    const float b = bavg[0];
    bf16* yh = Yh + (size_t)row * Wd;
    bf16* ym = Ym + (size_t)row * Wd;
    for (int h = tid; h < Wd; h += 256) {
        float s = b;
        #pragma unroll
        for (int k = 0; k < Kc; k++) s += sx[h + k] * wsh[k];
        bf16 sh, sm_;
        split2(s, sh, sm_);
        yh[h] = sh; ym[h] = sm_;
    }
}

// ---------------- bf16x3 mma.sync GEMM, 128x128 CTA tile, 64x32 warp tile, 2 CTA/SM ----------------
#define MMA16(cc, aa, bb) \
    asm volatile("mma.sync.aligned.m16n8k16.row.col.f32.bf16.bf16.f32 " \
        "{%0,%1,%2,%3},{%4,%5,%6,%7},{%8,%9},{%0,%1,%2,%3};" \
        : "+f"((cc)[0]), "+f"((cc)[1]), "+f"((cc)[2]), "+f"((cc)[3]) \
        : "r"((aa)[0]), "r"((aa)[1]), "r"((aa)[2]), "r"((aa)[3]), \
          "r"((bb)[0]), "r"((bb)[1]))

#define BK 32
#define TILE_W 2048            // 128 rows x 16 words
#define STAGE_W (4*TILE_W)     // Ah,Am,Bh,Bm = 8192 words = 32KB
#define NSTAGE 3
#define GEMM_SMEM (NSTAGE*STAGE_W*4)   // 98304 bytes

__global__ __launch_bounds__(256, 2) void gemm_mma_kernel(
    const bf16* __restrict__ Ah, const bf16* __restrict__ Am,
    const bf16* __restrict__ Bh, const bf16* __restrict__ Bm,
    const float* __restrict__ bias, float* __restrict__ C,
    int Kd, int N, size_t szB, size_t szBias, size_t szC)
{
    extern __shared__ uint32_t sm[];
    const uint32_t sbase = smem_u32(sm);
    const int z = blockIdx.z;
    Bh   += (size_t)z * szB;
    Bm   += (size_t)z * szB;
    bias += (size_t)z * szBias;
    C    += (size_t)z * szC;

    const int tid = threadIdx.x;
    const int wid = tid >> 5, lane = tid & 31;
    const int g = lane >> 2, t = lane & 3;
    const int wm = (wid >> 2) * 64;       // 2 m-warp groups
    const int wn = (wid & 3) * 32;        // 4 n-warp groups
    const int bm = blockIdx.y * 128, bn = blockIdx.x * 128;

    // cp.async mapping: 512 16B-groups per tile; thread covers tid, tid+256
    const int r0 = tid >> 2, c0 = tid & 3;
    const int r1 = r0 + 64;
    const uint32_t d0 = (uint32_t)(r0 * 16 + ((c0 ^ ((r0 >> 1) & 3)) << 2)) * 4;
    const uint32_t d1 = (uint32_t)(r1 * 16 + ((c0 ^ ((r1 >> 1) & 3)) << 2)) * 4;

    const bf16* a0h = Ah + (size_t)(bm + r0) * Kd + c0 * 8;
    const bf16* a0m = Am + (size_t)(bm + r0) * Kd + c0 * 8;
    const bf16* a1h = Ah + (size_t)(bm + r1) * Kd + c0 * 8;
    const bf16* a1m = Am + (size_t)(bm + r1) * Kd + c0 * 8;
    const bf16* b0h = Bh + (size_t)(bn + r0) * Kd + c0 * 8;
    const bf16* b0m = Bm + (size_t)(bn + r0) * Kd + c0 * 8;
    const bf16* b1h = Bh + (size_t)(bn + r1) * Kd + c0 * 8;
    const bf16* b1m = Bm + (size_t)(bn + r1) * Kd + c0 * 8;

    float acc[4][4][4];
    #pragma unroll
    for (int mt = 0; mt < 4; mt++)
        #pragma unroll
        for (int nt = 0; nt < 4; nt++)
            #pragma unroll
            for (int e = 0; e < 4; e++) acc[mt][nt][e] = 0.0f;

    const int NC = Kd / BK;

    #define ISSUE(s, kpos) do { \
        uint32_t _sb = sbase + (uint32_t)(s) * (STAGE_W * 4); \
        cp16(_sb + d0,                   a0h + (kpos)); \
        cp16(_sb + d1,                   a1h + (kpos)); \
        cp16(_sb + TILE_W * 4 + d0,      a0m + (kpos)); \
        cp16(_sb + TILE_W * 4 + d1,      a1m + (kpos)); \
        cp16(_sb + 2 * TILE_W * 4 + d0,  b0h + (kpos)); \
        cp16(_sb + 2 * TILE_W * 4 + d1,  b1h + (kpos)); \
        cp16(_sb + 3 * TILE_W * 4 + d0,  b0m + (kpos)); \
        cp16(_sb + 3 * TILE_W * 4 + d1,  b1m + (kpos)); \
        asm volatile("cp.async.commit_group;" ::: "memory"); \
    } while (0)

    ISSUE(0, 0);
    ISSUE(1, BK);

    for (int i = 0; i < NC; i++) {
        if (i + 1 < NC) asm volatile("cp.async.wait_group 1;" ::: "memory");
        else            asm volatile("cp.async.wait_group 0;" ::: "memory");
        __syncthreads();
        if (i + 2 < NC) {
            int s = i + 2; s = s - (s / 3) * 3;
            ISSUE(s, (i + 2) * BK);
        }

        int bsel = i - (i / 3) * 3;
        const uint32_t* sAh = sm + bsel * STAGE_W;
        const uint32_t* sAm = sAh + TILE_W;
        const uint32_t* sBh = sAm + TILE_W;
        const uint32_t* sBm = sBh + TILE_W;

        #pragma unroll
        for (int st = 0; st < 2; st++) {
            const int kb = st * 8;
            uint32_t bh[4][2], bmr[4][2];
            #pragma unroll
            for (int nt = 0; nt < 4; nt++) {
                int rb = wn + nt * 8 + g;
                int rx = ((rb >> 1) & 3) << 2;
                int i0 = rb * 16 + (kb ^ rx) + t;
                int i4 = rb * 16 + ((kb + 4) ^ rx) + t;
                bh[nt][0]  = sBh[i0]; bh[nt][1]  = sBh[i4];
                bmr[nt][0] = sBm[i0]; bmr[nt][1] = sBm[i4];
            }
            #pragma unroll
            for (int mt = 0; mt < 4; mt++) {
                int r0_ = wm + mt * 16 + g;
                int rx = ((r0_ >> 1) & 3) << 2;
                int i0 = r0_ * 16 + (kb ^ rx) + t;
                int i4 = r0_ * 16 + ((kb + 4) ^ rx) + t;
                uint32_t ah[4], am_[4];
                ah[0] = sAh[i0]; ah[1] = sAh[i0 + 128];
                ah[2] = sAh[i4]; ah[3] = sAh[i4 + 128];
                am_[0] = sAm[i0]; am_[1] = sAm[i0 + 128];
                am_[2] = sAm[i4]; am_[3] = sAm[i4 + 128];
                #pragma unroll
                for (int nt = 0; nt < 4; nt++) {
                    MMA16(acc[mt][nt], ah,  bh[nt]);
                    MMA16(acc[mt][nt], ah,  bmr[nt]);
                    MMA16(acc[mt][nt], am_, bh[nt]);
                }
            }
        }
        __syncthreads();
    }
    #undef ISSUE

    // epilogue
    #pragma unroll
    for (int mt = 0; mt < 4; mt++) {
        #pragma unroll
        for (int nt = 0; nt < 4; nt++) {
            int col = bn + wn + nt * 8 + 2 * t;
            float b0 = __ldg(&bias[col]);
            float b1 = __ldg(&bias[col + 1]);
            float* p0 = C + (size_t)(bm + wm + mt * 16 + g) * N + col;
            float2 o0 = make_float2(acc[mt][nt][0] + b0, acc[mt][nt][1] + b1);
            float2 o1 = make_float2(acc[mt][nt][2] + b0, acc[mt][nt][3] + b1);
            *(float2*)p0 = o0;
            *(float2*)(p0 + 8 * N) = o1;
        }
    }
}

// ---------------- FFT attention (twiddle table, writes 2x bf16) ----------------
__device__ __forceinline__ void fft1024_stages(float2* s, const float2* Tw, int tid, bool inv) {
    #pragma unroll
    for (int stage = 0; stage < 10; ++stage) {
        const int half = 1 << stage;
        #pragma unroll
        for (int r = 0; r < 2; ++r) {
            int b = tid + (r << 8);
            int pos = b & (half - 1);
            int i0 = ((b >> stage) << (stage + 1)) + pos;
            int i1 = i0 + half;
            float2 w = Tw[pos << (9 - stage)];
            float cs = w.x;
            float sn = inv ? -w.y : w.y;
            float2 x1 = s[i1];
            float2 t = make_float2(x1.x * cs - x1.y * sn, x1.x * sn + x1.y * cs);
            float2 x0 = s[i0];
            s[i0] = make_float2(x0.x + t.x, x0.y + t.y);
            s[i1] = make_float2(x0.x - t.x, x0.y - t.y);
        }
        __syncthreads();
    }
}

__global__ __launch_bounds__(256) void fft_attn_kernel(
    const float* __restrict__ Q, const float* __restrict__ Kx,
    const float* __restrict__ V,
    bf16* __restrict__ Oh, bf16* __restrict__ Om)
{
    __shared__ float2 Z[1024];
    __shared__ float2 Aw[1024];
    __shared__ float2 Tw[512];
    const int row = blockIdx.x;
    const int tid = threadIdx.x;
    const float* qr = Q  + (size_t)row * Pd;
    const float* kr = Kx + (size_t)row * Pd;
    const float* vr = V  + (size_t)row * Pd;

    for (int j = tid; j < 512; j += 256) {
        float sn, cs;
        __sincosf(-3.14159265358979323846f * (float)j / 512.0f, &sn, &cs);
        Tw[j] = make_float2(cs, sn);
    }

    for (int i = tid; i < 1024; i += 256) {
        int rdx = __brev((unsigned)i) >> 22;
        Z[rdx] = make_float2(qr[i], kr[i]);
    }
    __syncthreads();
    fft1024_stages(Z, Tw, tid, false);

    const float inv_scale = 1.0f / 32.0f;
    for (int i = tid; i < 1024; i += 256) {
        float2 zj = Z[i];
        float2 zn = Z[(1024 - i) & 1023];
        float Qx = 0.5f * (zj.x + zn.x);
        float Qy = 0.5f * (zj.y - zn.y);
        float Kxr = 0.5f * (zj.y + zn.y);
        float Kyr = -0.5f * (zj.x - zn.x);
        float Ax = Kxr * Qx + Kyr * Qy;
        float Ay = Kyr * Qx - Kxr * Qy;
        Aw[i] = make_float2(Ax * inv_scale, Ay * inv_scale);
    }
    __syncthreads();

    for (int i = tid; i < 1024; i += 256) {
        int rdx = __brev((unsigned)i) >> 22;
        Z[rdx] = make_float2(vr[i], 0.0f);
    }
    __syncthreads();
    fft1024_stages(Z, Tw, tid, false);

    for (int i = tid; i < 1024; i += 256) {
        float2 vf = Z[i], a = Aw[i];
        Aw[i] = make_float2(vf.x * a.x - vf.y * a.y, vf.x * a.y + vf.y * a.x);
    }
    __syncthreads();

    for (int i = tid; i < 1024; i += 256) {
        int rdx = __brev((unsigned)i) >> 22;
        Z[rdx] = Aw[i];
    }
    __syncthreads();
    fft1024_stages(Z, Tw, tid, true);

    bf16* oh = Oh + (size_t)row * Pd;
    bf16* om = Om + (size_t)row * Pd;
    const float invN = 1.0f / 1024.0f;
    for (int i = tid; i < 1024; i += 256) {
        float s = Z[i].x * invN;
        bf16 sh, sm_;
        split2(s, sh, sm_);
        oh[i] = sh; om[i] = sm_;
    }
}

// ---------------- launch ----------------
extern "C" void kernel_launch(void* const* d_in, const int* in_sizes, int n_in,
                              void* d_out, int out_size) {
    (void)in_sizes; (void)n_in; (void)out_size;
    const float* x      = (const float*)d_in[0];
    const float* conv_w = (const float*)d_in[1];
    const float* conv_b = (const float*)d_in[2];
    const float* wq     = (const float*)d_in[3];
    const float* bq     = (const float*)d_in[4];
    const float* wk     = (const float*)d_in[5];
    const float* bk     = (const float*)d_in[6];
    const float* wv     = (const float*)d_in[7];
    const float* bv     = (const float*)d_in[8];
    const float* wo     = (const float*)d_in[9];
    const float* bo     = (const float*)d_in[10];
    float* out = (float*)d_out;

    float *xb, *qkv, *bqkv, *wavg, *bavg;
    bf16 *ch, *cm, *ph, *pm;
    bf16 *wqkvh, *wqkvm, *woh, *wom;
    cudaGetSymbolAddress((void**)&xb,    g_x);
    cudaGetSymbolAddress((void**)&ch,    g_ch);
    cudaGetSymbolAddress((void**)&cm,    g_cm);
    cudaGetSymbolAddress((void**)&qkv,   g_qkv);
    cudaGetSymbolAddress((void**)&ph,    g_ph);
    cudaGetSymbolAddress((void**)&pm,    g_pm);
    cudaGetSymbolAddress((void**)&wqkvh, g_wqkvh);
    cudaGetSymbolAddress((void**)&wqkvm, g_wqkvm);
    cudaGetSymbolAddress((void**)&woh,   g_woh);
    cudaGetSymbolAddress((void**)&wom,   g_wom);
    cudaGetSymbolAddress((void**)&bqkv,  g_bqkv);
    cudaGetSymbolAddress((void**)&wavg,  g_wavg);
    cudaGetSymbolAddress((void**)&bavg,  g_bavg);

    cudaFuncSetAttribute(gemm_mma_kernel,
                         cudaFuncAttributeMaxDynamicSharedMemorySize, GEMM_SMEM);

    const size_t LPW = (size_t)Ld * Pd * Wd;   // 4M elements

    avg_conv_kernel<<<1, 64>>>(conv_w, conv_b, wavg, bavg);

    split2_kernel<<<1024, 256>>>(wq, wqkvh,           wqkvm,           (int)(LPW / 8));
    split2_kernel<<<1024, 256>>>(wk, wqkvh + LPW,     wqkvm + LPW,     (int)(LPW / 8));
    split2_kernel<<<1024, 256>>>(wv, wqkvh + 2 * LPW, wqkvm + 2 * LPW, (int)(LPW / 8));
    split2_kernel<<<1024, 256>>>(wo, woh,             wom,             (int)(LPW / 8));

    cudaMemcpyAsync(bqkv,               bq, Ld * Pd * 4, cudaMemcpyDeviceToDevice);
    cudaMemcpyAsync(bqkv + Ld * Pd,     bk, Ld * Pd * 4, cudaMemcpyDeviceToDevice);
    cudaMemcpyAsync(bqkv + 2 * Ld * Pd, bv, Ld * Pd * 4, cudaMemcpyDeviceToDevice);

    const size_t RP = (size_t)ROWS * Pd;

    for (int l = 0; l < Ld; l++) {
        const float* xin = (l == 0) ? x : xb;
        float* xout = (l == Ld - 1) ? out : xb;

        conv_row_kernel<<<ROWS, 256>>>(xin, ch, cm, wavg + l * Kc, bavg + l);

        dim3 gq(Pd / 128, ROWS / 128, 3);     // (8, 32, 3)
        gemm_mma_kernel<<<gq, 256, GEMM_SMEM>>>(
            ch, cm,
            wqkvh + (size_t)l * Pd * Wd, wqkvm + (size_t)l * Pd * Wd,
            bqkv + (size_t)l * Pd, qkv,
            Wd, Pd, LPW, (size_t)Ld * Pd, RP);

        fft_attn_kernel<<<ROWS, 256>>>(qkv, qkv + RP, qkv + 2 * RP, ph, pm);

        dim3 go(Wd / 128, ROWS / 128, 1);     // (16, 32, 1)
        gemm_mma_kernel<<<go, 256, GEMM_SMEM>>>(
            ph, pm,
            woh + (size_t)l * Wd * Pd, wom + (size_t)l * Wd * Pd,
            bo + (size_t)l * Wd, xout,
            Pd, Wd, 0, 0, 0);
    }
}

// round 9
// speedup vs baseline: 1.0736x; 1.0736x over previous
#include <cuda_runtime.h>
#include <cuda_bf16.h>
#include <cstdint>

#define BSZ 32
#define CNT 128
#define Wd  2048
#define Pd  1024
#define Ed  8
#define Kc  25
#define Ld  2
#define ROWS (BSZ*CNT)   // 4096

typedef __nv_bfloat16 bf16;

// ---------------- scratch ----------------
__device__ float g_x[ROWS*Wd];
__device__ bf16  g_ch[ROWS*Wd];
__device__ bf16  g_cm[ROWS*Wd];
__device__ float g_qkv[3*ROWS*Pd];
__device__ bf16  g_ph[ROWS*Pd];
__device__ bf16  g_pm[ROWS*Pd];
__device__ bf16  g_wqkvh[3*Ld*Pd*Wd];
__device__ bf16  g_wqkvm[3*Ld*Pd*Wd];
__device__ bf16  g_woh[Ld*Wd*Pd];
__device__ bf16  g_wom[Ld*Wd*Pd];
__device__ float g_bqkv[3*Ld*Pd];
__device__ float g_wavg[Ld*Kc];
__device__ float g_bavg[Ld];

// ---------------- helpers ----------------
__device__ __forceinline__ uint32_t smem_u32(const void* p) {
    uint32_t a;
    asm("{ .reg .u64 t; cvta.to.shared.u64 t, %1; cvt.u32.u64 %0, t; }" : "=r"(a) : "l"(p));
    return a;
}
__device__ __forceinline__ void cp16(uint32_t dst, const void* src) {
    asm volatile("cp.async.cg.shared.global [%0], [%1], 16;" :: "r"(dst), "l"(src));
}
__device__ __forceinline__ void split2(float x, bf16& h, bf16& m) {
    h = __float2bfloat16(x);
    m = __float2bfloat16(x - __bfloat162float(h));
}
__device__ __forceinline__ uint32_t pack2(bf16 a, bf16 b) {
    return (uint32_t)__bfloat16_as_ushort(a) | ((uint32_t)__bfloat16_as_ushort(b) << 16);
}

// ---------------- weight split fp32 -> 2x bf16 ----------------
__global__ void split2_kernel(const float* __restrict__ src, bf16* __restrict__ h,
                              bf16* __restrict__ m, int n8) {
    int i = blockIdx.x * blockDim.x + threadIdx.x;
    int stride = gridDim.x * blockDim.x;
    for (; i < n8; i += stride) {
        float4 v0 = ((const float4*)src)[2 * i];
        float4 v1 = ((const float4*)src)[2 * i + 1];
        float v[8] = {v0.x, v0.y, v0.z, v0.w, v1.x, v1.y, v1.z, v1.w};
        bf16 hh[8], mm_[8];
        #pragma unroll
        for (int e = 0; e < 8; e++) split2(v[e], hh[e], mm_[e]);
        uint4 u;
        u.x = pack2(hh[0], hh[1]); u.y = pack2(hh[2], hh[3]);
        u.z = pack2(hh[4], hh[5]); u.w = pack2(hh[6], hh[7]);
        ((uint4*)h)[i] = u;
        u.x = pack2(mm_[0], mm_[1]); u.y = pack2(mm_[2], mm_[3]);
        u.z = pack2(mm_[4], mm_[5]); u.w = pack2(mm_[6], mm_[7]);
        ((uint4*)m)[i] = u;
    }
}

// ---------------- avg conv weights ----------------
__global__ void avg_conv_kernel(const float* __restrict__ cw, const float* __restrict__ cb,
                                float* __restrict__ wavg, float* __restrict__ bavg) {
    int idx = threadIdx.x;
    if (idx < Ld * Kc) {
        int l = idx / Kc, kk = idx % Kc;
        float s = 0.f;
        #pragma unroll
        for (int e = 0; e < Ed; e++) s += cw[(l * Ed + e) * Kc + kk];
        wavg[idx] = s * (1.0f / Ed);
    }
    if (idx < Ld) {
        float s = 0.f;
        #pragma unroll
        for (int e = 0; e < Ed; e++) s += cb[idx * Ed + e];
        bavg[idx] = s * (1.0f / Ed);
    }
}

// ---------------- 1D conv, writes 2x bf16 ----------------
__global__ __launch_bounds__(256) void conv_row_kernel(
    const float* __restrict__ X, bf16* __restrict__ Yh, bf16* __restrict__ Ym,
    const float* __restrict__ wavg, const float* __restrict__ bavg)
{
    __shared__ float sx[Wd + Kc - 1];
    __shared__ float wsh[Kc];
    const int row = blockIdx.x;
    const int tid = threadIdx.x;
    const float* xr = X + (size_t)row * Wd;

    for (int i = tid; i < Wd + Kc - 1; i += 256) {
        int src = i - (Kc / 2);
        sx[i] = (src >= 0 && src < Wd) ? xr[src] : 0.0f;
    }
    if (tid < Kc) wsh[tid] = wavg[tid];
    __syncthreads();

    const float b = bavg[0];
    bf16* yh = Yh + (size_t)row * Wd;
    bf16* ym = Ym + (size_t)row * Wd;
    for (int h = tid; h < Wd; h += 256) {
        float s = b;
        #pragma unroll
        for (int k = 0; k < Kc; k++) s += sx[h + k] * wsh[k];
        bf16 sh, sm_;
        split2(s, sh, sm_);
        yh[h] = sh; ym[h] = sm_;
    }
}

// ---------------- bf16x3 mma.sync GEMM, ldmatrix fragments ----------------
#define MMA16(cc, aa, bb) \
    asm volatile("mma.sync.aligned.m16n8k16.row.col.f32.bf16.bf16.f32 " \
        "{%0,%1,%2,%3},{%4,%5,%6,%7},{%8,%9},{%0,%1,%2,%3};" \
        : "+f"((cc)[0]), "+f"((cc)[1]), "+f"((cc)[2]), "+f"((cc)[3]) \
        : "r"((aa)[0]), "r"((aa)[1]), "r"((aa)[2]), "r"((aa)[3]), \
          "r"((bb)[0]), "r"((bb)[1]))

#define LDMX4(r0, r1, r2, r3, a) \
    asm volatile("ldmatrix.sync.aligned.m8n8.x4.shared.b16 {%0,%1,%2,%3}, [%4];" \
        : "=r"(r0), "=r"(r1), "=r"(r2), "=r"(r3) : "r"(a))

#define BK 32
#define TILE_W 2048            // 128 rows x 16 words
#define STAGE_W (4*TILE_W)     // Ah,Am,Bh,Bm = 8192 words = 32KB
#define NSTAGE 3
#define GEMM_SMEM (NSTAGE*STAGE_W*4)   // 98304 bytes

__global__ __launch_bounds__(256, 2) void gemm_mma_kernel(
    const bf16* __restrict__ Ah, const bf16* __restrict__ Am,
    const bf16* __restrict__ Bh, const bf16* __restrict__ Bm,
    const float* __restrict__ bias, float* __restrict__ C,
    int Kd, int N, size_t szB, size_t szBias, size_t szC)
{
    extern __shared__ uint32_t sm[];
    const uint32_t sbase = smem_u32(sm);
    const int z = blockIdx.z;
    Bh   += (size_t)z * szB;
    Bm   += (size_t)z * szB;
    bias += (size_t)z * szBias;
    C    += (size_t)z * szC;

    const int tid = threadIdx.x;
    const int wid = tid >> 5, lane = tid & 31;
    const int g = lane >> 2, t = lane & 3;
    const int wm = (wid >> 2) * 64;       // 2 m-warp groups
    const int wn = (wid & 3) * 32;        // 4 n-warp groups
    const int bm = blockIdx.y * 128, bn = blockIdx.x * 128;

    // ---- ldmatrix per-lane byte offsets within a tile ----
    // swizzled word index for (row, wordcol): row*16 + (((wc>>2) ^ ((row>>1)&3))<<2) + (wc&3)
    const int lr = lane & 7;
    const int ls = lane >> 3;   // 0..3 (matrix select)
    uint32_t Aoff[2][4], Boff[2][2];
    #pragma unroll
    for (int st = 0; st < 2; st++) {
        #pragma unroll
        for (int mt = 0; mt < 4; mt++) {
            int row = wm + mt * 16 + lr + (ls & 1) * 8;
            int wc2 = st * 2 + (ls >> 1);              // wordcol>>2
            Aoff[st][mt] = (uint32_t)(row * 16 + ((wc2 ^ ((row >> 1) & 3)) << 2)) * 4;
        }
        #pragma unroll
        for (int p = 0; p < 2; p++) {
            int row = wn + p * 16 + (ls >> 1) * 8 + lr;
            int wc2 = st * 2 + (ls & 1);
            Boff[st][p] = (uint32_t)(row * 16 + ((wc2 ^ ((row >> 1) & 3)) << 2)) * 4;
        }
    }

    // cp.async mapping: 512 16B-groups per tile; thread covers tid, tid+256
    const int r0 = tid >> 2, c0 = tid & 3;
    const int r1 = r0 + 64;
    const uint32_t d0 = (uint32_t)(r0 * 16 + ((c0 ^ ((r0 >> 1) & 3)) << 2)) * 4;
    const uint32_t d1 = (uint32_t)(r1 * 16 + ((c0 ^ ((r1 >> 1) & 3)) << 2)) * 4;

    const bf16* a0h = Ah + (size_t)(bm + r0) * Kd + c0 * 8;
    const bf16* a0m = Am + (size_t)(bm + r0) * Kd + c0 * 8;
    const bf16* a1h = Ah + (size_t)(bm + r1) * Kd + c0 * 8;
    const bf16* a1m = Am + (size_t)(bm + r1) * Kd + c0 * 8;
    const bf16* b0h = Bh + (size_t)(bn + r0) * Kd + c0 * 8;
    const bf16* b0m = Bm + (size_t)(bn + r0) * Kd + c0 * 8;
    const bf16* b1h = Bh + (size_t)(bn + r1) * Kd + c0 * 8;
    const bf16* b1m = Bm + (size_t)(bn + r1) * Kd + c0 * 8;

    float acc[4][4][4];
    #pragma unroll
    for (int mt = 0; mt < 4; mt++)
        #pragma unroll
        for (int nt = 0; nt < 4; nt++)
            #pragma unroll
            for (int e = 0; e < 4; e++) acc[mt][nt][e] = 0.0f;

    const int NC = Kd / BK;

    #define ISSUE(s, kpos) do { \
        uint32_t _sb = sbase + (uint32_t)(s) * (STAGE_W * 4); \
        cp16(_sb + d0,                   a0h + (kpos)); \
        cp16(_sb + d1,                   a1h + (kpos)); \
        cp16(_sb + TILE_W * 4 + d0,      a0m + (kpos)); \
        cp16(_sb + TILE_W * 4 + d1,      a1m + (kpos)); \
        cp16(_sb + 2 * TILE_W * 4 + d0,  b0h + (kpos)); \
        cp16(_sb + 2 * TILE_W * 4 + d1,  b1h + (kpos)); \
        cp16(_sb + 3 * TILE_W * 4 + d0,  b0m + (kpos)); \
        cp16(_sb + 3 * TILE_W * 4 + d1,  b1m + (kpos)); \
        asm volatile("cp.async.commit_group;" ::: "memory"); \
    } while (0)

    ISSUE(0, 0);
    ISSUE(1, BK);

    for (int i = 0; i < NC; i++) {
        if (i + 1 < NC) asm volatile("cp.async.wait_group 1;" ::: "memory");
        else            asm volatile("cp.async.wait_group 0;" ::: "memory");
        __syncthreads();
        if (i + 2 < NC) {
            int s = i + 2; s = s - (s / 3) * 3;
            ISSUE(s, (i + 2) * BK);
        }

        int bsel = i - (i / 3) * 3;
        const uint32_t sAh = sbase + (uint32_t)bsel * (STAGE_W * 4);
        const uint32_t sAm = sAh + TILE_W * 4;
        const uint32_t sBh = sAm + TILE_W * 4;
        const uint32_t sBm = sBh + TILE_W * 4;

        #pragma unroll
        for (int st = 0; st < 2; st++) {
            uint32_t bh[4][2], bmr[4][2];
            LDMX4(bh[0][0], bh[0][1], bh[1][0], bh[1][1], sBh + Boff[st][0]);
            LDMX4(bh[2][0], bh[2][1], bh[3][0], bh[3][1], sBh + Boff[st][1]);
            LDMX4(bmr[0][0], bmr[0][1], bmr[1][0], bmr[1][1], sBm + Boff[st][0]);
            LDMX4(bmr[2][0], bmr[2][1], bmr[3][0], bmr[3][1], sBm + Boff[st][1]);
            #pragma unroll
            for (int mt = 0; mt < 4; mt++) {
                uint32_t ah[4], am_[4];
                LDMX4(ah[0], ah[1], ah[2], ah[3], sAh + Aoff[st][mt]);
                LDMX4(am_[0], am_[1], am_[2], am_[3], sAm + Aoff[st][mt]);
                #pragma unroll
                for (int nt = 0; nt < 4; nt++) {
                    MMA16(acc[mt][nt], ah,  bh[nt]);
                    MMA16(acc[mt][nt], ah,  bmr[nt]);
                    MMA16(acc[mt][nt], am_, bh[nt]);
                }
            }
        }
        __syncthreads();
    }
    #undef ISSUE

    // epilogue
    #pragma unroll
    for (int mt = 0; mt < 4; mt++) {
        #pragma unroll
        for (int nt = 0; nt < 4; nt++) {
            int col = bn + wn + nt * 8 + 2 * t;
            float b0 = __ldg(&bias[col]);
            float b1 = __ldg(&bias[col + 1]);
            float* p0 = C + (size_t)(bm + wm + mt * 16 + g) * N + col;
            float2 o0 = make_float2(acc[mt][nt][0] + b0, acc[mt][nt][1] + b1);
            float2 o1 = make_float2(acc[mt][nt][2] + b0, acc[mt][nt][3] + b1);
            *(float2*)p0 = o0;
            *(float2*)(p0 + 8 * N) = o1;
        }
    }
}

// ---------------- FFT attention (twiddle table, writes 2x bf16) ----------------
__device__ __forceinline__ void fft1024_stages(float2* s, const float2* Tw, int tid, bool inv) {
    #pragma unroll
    for (int stage = 0; stage < 10; ++stage) {
        const int half = 1 << stage;
        #pragma unroll
        for (int r = 0; r < 2; ++r) {
            int b = tid + (r << 8);
            int pos = b & (half - 1);
            int i0 = ((b >> stage) << (stage + 1)) + pos;
            int i1 = i0 + half;
            float2 w = Tw[pos << (9 - stage)];
            float cs = w.x;
            float sn = inv ? -w.y : w.y;
            float2 x1 = s[i1];
            float2 t = make_float2(x1.x * cs - x1.y * sn, x1.x * sn + x1.y * cs);
            float2 x0 = s[i0];
            s[i0] = make_float2(x0.x + t.x, x0.y + t.y);
            s[i1] = make_float2(x0.x - t.x, x0.y - t.y);
        }
        __syncthreads();
    }
}

__global__ __launch_bounds__(256) void fft_attn_kernel(
    const float* __restrict__ Q, const float* __restrict__ Kx,
    const float* __restrict__ V,
    bf16* __restrict__ Oh, bf16* __restrict__ Om)
{
    __shared__ float2 Z[1024];
    __shared__ float2 Aw[1024];
    __shared__ float2 Tw[512];
    const int row = blockIdx.x;
    const int tid = threadIdx.x;
    const float* qr = Q  + (size_t)row * Pd;
    const float* kr = Kx + (size_t)row * Pd;
    const float* vr = V  + (size_t)row * Pd;

    for (int j = tid; j < 512; j += 256) {
        float sn, cs;
        __sincosf(-3.14159265358979323846f * (float)j / 512.0f, &sn, &cs);
        Tw[j] = make_float2(cs, sn);
    }

    for (int i = tid; i < 1024; i += 256) {
        int rdx = __brev((unsigned)i) >> 22;
        Z[rdx] = make_float2(qr[i], kr[i]);
    }
    __syncthreads();
    fft1024_stages(Z, Tw, tid, false);

    const float inv_scale = 1.0f / 32.0f;
    for (int i = tid; i < 1024; i += 256) {
        float2 zj = Z[i];
        float2 zn = Z[(1024 - i) & 1023];
        float Qx = 0.5f * (zj.x + zn.x);
        float Qy = 0.5f * (zj.y - zn.y);
        float Kxr = 0.5f * (zj.y + zn.y);
        float Kyr = -0.5f * (zj.x - zn.x);
        float Ax = Kxr * Qx + Kyr * Qy;
        float Ay = Kyr * Qx - Kxr * Qy;
        Aw[i] = make_float2(Ax * inv_scale, Ay * inv_scale);
    }
    __syncthreads();

    for (int i = tid; i < 1024; i += 256) {
        int rdx = __brev((unsigned)i) >> 22;
        Z[rdx] = make_float2(vr[i], 0.0f);
    }
    __syncthreads();
    fft1024_stages(Z, Tw, tid, false);

    for (int i = tid; i < 1024; i += 256) {
        float2 vf = Z[i], a = Aw[i];
        Aw[i] = make_float2(vf.x * a.x - vf.y * a.y, vf.x * a.y + vf.y * a.x);
    }
    __syncthreads();

    for (int i = tid; i < 1024; i += 256) {
        int rdx = __brev((unsigned)i) >> 22;
        Z[rdx] = Aw[i];
    }
    __syncthreads();
    fft1024_stages(Z, Tw, tid, true);

    bf16* oh = Oh + (size_t)row * Pd;
    bf16* om = Om + (size_t)row * Pd;
    const float invN = 1.0f / 1024.0f;
    for (int i = tid; i < 1024; i += 256) {
        float s = Z[i].x * invN;
        bf16 sh, sm_;
        split2(s, sh, sm_);
        oh[i] = sh; om[i] = sm_;
    }
}

// ---------------- launch ----------------
extern "C" void kernel_launch(void* const* d_in, const int* in_sizes, int n_in,
                              void* d_out, int out_size) {
    (void)in_sizes; (void)n_in; (void)out_size;
    const float* x      = (const float*)d_in[0];
    const float* conv_w = (const float*)d_in[1];
    const float* conv_b = (const float*)d_in[2];
    const float* wq     = (const float*)d_in[3];
    const float* bq     = (const float*)d_in[4];
    const float* wk     = (const float*)d_in[5];
    const float* bk     = (const float*)d_in[6];
    const float* wv     = (const float*)d_in[7];
    const float* bv     = (const float*)d_in[8];
    const float* wo     = (const float*)d_in[9];
    const float* bo     = (const float*)d_in[10];
    float* out = (float*)d_out;

    float *xb, *qkv, *bqkv, *wavg, *bavg;
    bf16 *ch, *cm, *ph, *pm;
    bf16 *wqkvh, *wqkvm, *woh, *wom;
    cudaGetSymbolAddress((void**)&xb,    g_x);
    cudaGetSymbolAddress((void**)&ch,    g_ch);
    cudaGetSymbolAddress((void**)&cm,    g_cm);
    cudaGetSymbolAddress((void**)&qkv,   g_qkv);
    cudaGetSymbolAddress((void**)&ph,    g_ph);
    cudaGetSymbolAddress((void**)&pm,    g_pm);
    cudaGetSymbolAddress((void**)&wqkvh, g_wqkvh);
    cudaGetSymbolAddress((void**)&wqkvm, g_wqkvm);
    cudaGetSymbolAddress((void**)&woh,   g_woh);
    cudaGetSymbolAddress((void**)&wom,   g_wom);
    cudaGetSymbolAddress((void**)&bqkv,  g_bqkv);
    cudaGetSymbolAddress((void**)&wavg,  g_wavg);
    cudaGetSymbolAddress((void**)&bavg,  g_bavg);

    cudaFuncSetAttribute(gemm_mma_kernel,
                         cudaFuncAttributeMaxDynamicSharedMemorySize, GEMM_SMEM);

    const size_t LPW = (size_t)Ld * Pd * Wd;   // 4M elements

    avg_conv_kernel<<<1, 64>>>(conv_w, conv_b, wavg, bavg);

    split2_kernel<<<1024, 256>>>(wq, wqkvh,           wqkvm,           (int)(LPW / 8));
    split2_kernel<<<1024, 256>>>(wk, wqkvh + LPW,     wqkvm + LPW,     (int)(LPW / 8));
    split2_kernel<<<1024, 256>>>(wv, wqkvh + 2 * LPW, wqkvm + 2 * LPW, (int)(LPW / 8));
    split2_kernel<<<1024, 256>>>(wo, woh,             wom,             (int)(LPW / 8));

    cudaMemcpyAsync(bqkv,               bq, Ld * Pd * 4, cudaMemcpyDeviceToDevice);
    cudaMemcpyAsync(bqkv + Ld * Pd,     bk, Ld * Pd * 4, cudaMemcpyDeviceToDevice);
    cudaMemcpyAsync(bqkv + 2 * Ld * Pd, bv, Ld * Pd * 4, cudaMemcpyDeviceToDevice);

    const size_t RP = (size_t)ROWS * Pd;

    for (int l = 0; l < Ld; l++) {
        const float* xin = (l == 0) ? x : xb;
        float* xout = (l == Ld - 1) ? out : xb;

        conv_row_kernel<<<ROWS, 256>>>(xin, ch, cm, wavg + l * Kc, bavg + l);

        dim3 gq(Pd / 128, ROWS / 128, 3);     // (8, 32, 3)
        gemm_mma_kernel<<<gq, 256, GEMM_SMEM>>>(
            ch, cm,
            wqkvh + (size_t)l * Pd * Wd, wqkvm + (size_t)l * Pd * Wd,
            bqkv + (size_t)l * Pd, qkv,
            Wd, Pd, LPW, (size_t)Ld * Pd, RP);

        fft_attn_kernel<<<ROWS, 256>>>(qkv, qkv + RP, qkv + 2 * RP, ph, pm);

        dim3 go(Wd / 128, ROWS / 128, 1);     // (16, 32, 1)
        gemm_mma_kernel<<<go, 256, GEMM_SMEM>>>(
            ph, pm,
            woh + (size_t)l * Wd * Pd, wom + (size_t)l * Wd * Pd,
            bo + (size_t)l * Wd, xout,
            Pd, Wd, 0, 0, 0);
    }
}

// round 10
// speedup vs baseline: 1.0796x; 1.0055x over previous
#include <cuda_runtime.h>
#include <cuda_bf16.h>
#include <cstdint>

#define BSZ 32
#define CNT 128
#define Wd  2048
#define Pd  1024
#define Ed  8
#define Kc  25
#define Ld  2
#define ROWS (BSZ*CNT)   // 4096

typedef __nv_bfloat16 bf16;

// ---------------- scratch ----------------
__device__ float g_x[ROWS*Wd];
__device__ bf16  g_ch[ROWS*Wd];
__device__ bf16  g_cm[ROWS*Wd];
__device__ float g_qkv[3*ROWS*Pd];
__device__ bf16  g_ph[ROWS*Pd];
__device__ bf16  g_pm[ROWS*Pd];
__device__ bf16  g_wqkvh[3*Ld*Pd*Wd];
__device__ bf16  g_wqkvm[3*Ld*Pd*Wd];
__device__ bf16  g_woh[Ld*Wd*Pd];
__device__ bf16  g_wom[Ld*Wd*Pd];
__device__ float g_bqkv[3*Ld*Pd];
__device__ float g_wavg[Ld*Kc];
__device__ float g_bavg[Ld];

// ---------------- helpers ----------------
__device__ __forceinline__ uint32_t smem_u32(const void* p) {
    uint32_t a;
    asm("{ .reg .u64 t; cvta.to.shared.u64 t, %1; cvt.u32.u64 %0, t; }" : "=r"(a) : "l"(p));
    return a;
}
__device__ __forceinline__ void cp16(uint32_t dst, const void* src) {
    asm volatile("cp.async.cg.shared.global [%0], [%1], 16;" :: "r"(dst), "l"(src));
}
__device__ __forceinline__ void split2(float x, bf16& h, bf16& m) {
    h = __float2bfloat16(x);
    m = __float2bfloat16(x - __bfloat162float(h));
}
__device__ __forceinline__ uint32_t pack2(bf16 a, bf16 b) {
    return (uint32_t)__bfloat16_as_ushort(a) | ((uint32_t)__bfloat16_as_ushort(b) << 16);
}

// ---------------- weight split fp32 -> 2x bf16 ----------------
__global__ void split2_kernel(const float* __restrict__ src, bf16* __restrict__ h,
                              bf16* __restrict__ m, int n8) {
    int i = blockIdx.x * blockDim.x + threadIdx.x;
    int stride = gridDim.x * blockDim.x;
    for (; i < n8; i += stride) {
        float4 v0 = ((const float4*)src)[2 * i];
        float4 v1 = ((const float4*)src)[2 * i + 1];
        float v[8] = {v0.x, v0.y, v0.z, v0.w, v1.x, v1.y, v1.z, v1.w};
        bf16 hh[8], mm_[8];
        #pragma unroll
        for (int e = 0; e < 8; e++) split2(v[e], hh[e], mm_[e]);
        uint4 u;
        u.x = pack2(hh[0], hh[1]); u.y = pack2(hh[2], hh[3]);
        u.z = pack2(hh[4], hh[5]); u.w = pack2(hh[6], hh[7]);
        ((uint4*)h)[i] = u;
        u.x = pack2(mm_[0], mm_[1]); u.y = pack2(mm_[2], mm_[3]);
        u.z = pack2(mm_[4], mm_[5]); u.w = pack2(mm_[6], mm_[7]);
        ((uint4*)m)[i] = u;
    }
}

// ---------------- avg conv weights ----------------
__global__ void avg_conv_kernel(const float* __restrict__ cw, const float* __restrict__ cb,
                                float* __restrict__ wavg, float* __restrict__ bavg) {
    int idx = threadIdx.x;
    if (idx < Ld * Kc) {
        int l = idx / Kc, kk = idx % Kc;
        float s = 0.f;
        #pragma unroll
        for (int e = 0; e < Ed; e++) s += cw[(l * Ed + e) * Kc + kk];
        wavg[idx] = s * (1.0f / Ed);
    }
    if (idx < Ld) {
        float s = 0.f;
        #pragma unroll
        for (int e = 0; e < Ed; e++) s += cb[idx * Ed + e];
        bavg[idx] = s * (1.0f / Ed);
    }
}

// ---------------- 1D conv, writes 2x bf16 ----------------
__global__ __launch_bounds__(256) void conv_row_kernel(
    const float* __restrict__ X, bf16* __restrict__ Yh, bf16* __restrict__ Ym,
    const float* __restrict__ wavg, const float* __restrict__ bavg)
{
    __shared__ float sx[Wd + Kc - 1];
    __shared__ float wsh[Kc];
    const int row = blockIdx.x;
    const int tid = threadIdx.x;
    const float* xr = X + (size_t)row * Wd;

    for (int i = tid; i < Wd + Kc - 1; i += 256) {
        int src = i - (Kc / 2);
        sx[i] = (src >= 0 && src < Wd) ? xr[src] : 0.0f;
    }
    if (tid < Kc) wsh[tid] = wavg[tid];
    __syncthreads();

    const float b = bavg[0];
    bf16* yh = Yh + (size_t)row * Wd;
    bf16* ym = Ym + (size_t)row * Wd;
    for (int h = tid; h < Wd; h += 256) {
        float s = b;
        #pragma unroll
        for (int k = 0; k < Kc; k++) s += sx[h + k] * wsh[k];
        bf16 sh, sm_;
        split2(s, sh, sm_);
        yh[h] = sh; ym[h] = sm_;
    }
}

// ---------------- bf16x3 mma.sync GEMM, ldmatrix + warp stagger ----------------
#define MMA16(cc, aa, bb) \
    asm volatile("mma.sync.aligned.m16n8k16.row.col.f32.bf16.bf16.f32 " \
        "{%0,%1,%2,%3},{%4,%5,%6,%7},{%8,%9},{%0,%1,%2,%3};" \
        : "+f"((cc)[0]), "+f"((cc)[1]), "+f"((cc)[2]), "+f"((cc)[3]) \
        : "r"((aa)[0]), "r"((aa)[1]), "r"((aa)[2]), "r"((aa)[3]), \
          "r"((bb)[0]), "r"((bb)[1]))

#define LDMX4(r0, r1, r2, r3, a) \
    asm volatile("ldmatrix.sync.aligned.m8n8.x4.shared.b16 {%0,%1,%2,%3}, [%4];" \
        : "=r"(r0), "=r"(r1), "=r"(r2), "=r"(r3) : "r"(a))

#define BK 32
#define TILE_W 2048            // 128 rows x 16 words
#define STAGE_W (4*TILE_W)     // Ah,Am,Bh,Bm = 8192 words = 32KB
#define NSTAGE 3
#define GEMM_SMEM (NSTAGE*STAGE_W*4)   // 98304 bytes

__global__ __launch_bounds__(256, 2) void gemm_mma_kernel(
    const bf16* __restrict__ Ah, const bf16* __restrict__ Am,
    const bf16* __restrict__ Bh, const bf16* __restrict__ Bm,
    const float* __restrict__ bias, float* __restrict__ C,
    int Kd, int N, size_t szB, size_t szBias, size_t szC)
{
    extern __shared__ uint32_t sm[];
    const uint32_t sbase = smem_u32(sm);
    const int z = blockIdx.z;
    Bh   += (size_t)z * szB;
    Bm   += (size_t)z * szB;
    bias += (size_t)z * szBias;
    C    += (size_t)z * szC;

    const int tid = threadIdx.x;
    const int wid = tid >> 5, lane = tid & 31;
    const int g = lane >> 2, t = lane & 3;
    const int wm = (wid >> 2) * 64;       // 2 m-warp groups
    const int wn = (wid & 3) * 32;        // 4 n-warp groups
    const int bm = blockIdx.y * 128, bn = blockIdx.x * 128;
    const int stA = wid & 1;              // per-warp substep stagger

    // ---- ldmatrix per-lane byte offsets (bases; +1024B per 16-row step) ----
    const int lr = lane & 7;
    const int ls = lane >> 3;   // 0..3 (matrix select)
    uint32_t Abase[2], Bbase[2];
    #pragma unroll
    for (int st = 0; st < 2; st++) {
        int arow = wm + lr + (ls & 1) * 8;
        int awc2 = st * 2 + (ls >> 1);
        Abase[st] = (uint32_t)(arow * 16 + ((awc2 ^ ((arow >> 1) & 3)) << 2)) * 4;
        int brow = wn + (ls >> 1) * 8 + lr;
        int bwc2 = st * 2 + (ls & 1);
        Bbase[st] = (uint32_t)(brow * 16 + ((bwc2 ^ ((brow >> 1) & 3)) << 2)) * 4;
    }

    // cp.async mapping: 512 16B-groups per tile; thread covers tid, tid+256
    const int r0 = tid >> 2, c0 = tid & 3;
    const int r1 = r0 + 64;
    const uint32_t d0 = (uint32_t)(r0 * 16 + ((c0 ^ ((r0 >> 1) & 3)) << 2)) * 4;
    const uint32_t d1 = (uint32_t)(r1 * 16 + ((c0 ^ ((r1 >> 1) & 3)) << 2)) * 4;

    const bf16* a0h = Ah + (size_t)(bm + r0) * Kd + c0 * 8;
    const bf16* a0m = Am + (size_t)(bm + r0) * Kd + c0 * 8;
    const bf16* a1h = Ah + (size_t)(bm + r1) * Kd + c0 * 8;
    const bf16* a1m = Am + (size_t)(bm + r1) * Kd + c0 * 8;
    const bf16* b0h = Bh + (size_t)(bn + r0) * Kd + c0 * 8;
    const bf16* b0m = Bm + (size_t)(bn + r0) * Kd + c0 * 8;
    const bf16* b1h = Bh + (size_t)(bn + r1) * Kd + c0 * 8;
    const bf16* b1m = Bm + (size_t)(bn + r1) * Kd + c0 * 8;

    float acc[4][4][4];
    #pragma unroll
    for (int mt = 0; mt < 4; mt++)
        #pragma unroll
        for (int nt = 0; nt < 4; nt++)
            #pragma unroll
            for (int e = 0; e < 4; e++) acc[mt][nt][e] = 0.0f;

    const int NC = Kd / BK;

    #define ISSUE(s, kpos) do { \
        uint32_t _sb = sbase + (uint32_t)(s) * (STAGE_W * 4); \
        cp16(_sb + d0,                   a0h + (kpos)); \
        cp16(_sb + d1,                   a1h + (kpos)); \
        cp16(_sb + TILE_W * 4 + d0,      a0m + (kpos)); \
        cp16(_sb + TILE_W * 4 + d1,      a1m + (kpos)); \
        cp16(_sb + 2 * TILE_W * 4 + d0,  b0h + (kpos)); \
        cp16(_sb + 2 * TILE_W * 4 + d1,  b1h + (kpos)); \
        cp16(_sb + 3 * TILE_W * 4 + d0,  b0m + (kpos)); \
        cp16(_sb + 3 * TILE_W * 4 + d1,  b1m + (kpos)); \
        asm volatile("cp.async.commit_group;" ::: "memory"); \
    } while (0)

    ISSUE(0, 0);
    ISSUE(1, BK);

    for (int i = 0; i < NC; i++) {
        if (i + 1 < NC) asm volatile("cp.async.wait_group 1;" ::: "memory");
        else            asm volatile("cp.async.wait_group 0;" ::: "memory");
        __syncthreads();
        if (i + 2 < NC) {
            int s = i + 2; s = s - (s / 3) * 3;
            ISSUE(s, (i + 2) * BK);
        }

        int bsel = i - (i / 3) * 3;
        const uint32_t sAh = sbase + (uint32_t)bsel * (STAGE_W * 4);
        const uint32_t sAm = sAh + TILE_W * 4;
        const uint32_t sBh = sAm + TILE_W * 4;
        const uint32_t sBm = sBh + TILE_W * 4;

        #pragma unroll
        for (int s = 0; s < 2; s++) {
            const int st = s ^ stA;                 // staggered substep order
            const uint32_t ab = Abase[st];
            const uint32_t bb = Bbase[st];

            uint32_t bh[4][2], bmr[4][2];
            LDMX4(bh[0][0], bh[0][1], bh[1][0], bh[1][1], sBh + bb);
            LDMX4(bh[2][0], bh[2][1], bh[3][0], bh[3][1], sBh + bb + 1024);
            LDMX4(bmr[0][0], bmr[0][1], bmr[1][0], bmr[1][1], sBm + bb);
            LDMX4(bmr[2][0], bmr[2][1], bmr[3][0], bmr[3][1], sBm + bb + 1024);

            // one-ahead A pipeline
            uint32_t ah[2][4], am_[2][4];
            LDMX4(ah[0][0], ah[0][1], ah[0][2], ah[0][3], sAh + ab);
            LDMX4(am_[0][0], am_[0][1], am_[0][2], am_[0][3], sAm + ab);
            #pragma unroll
            for (int mt = 0; mt < 4; mt++) {
                const int cur = mt & 1, nxt = cur ^ 1;
                if (mt < 3) {
                    uint32_t ao = ab + (uint32_t)(mt + 1) * 1024;
                    LDMX4(ah[nxt][0], ah[nxt][1], ah[nxt][2], ah[nxt][3], sAh + ao);
                    LDMX4(am_[nxt][0], am_[nxt][1], am_[nxt][2], am_[nxt][3], sAm + ao);
                }
                #pragma unroll
                for (int nt = 0; nt < 4; nt++) {
                    MMA16(acc[mt][nt], ah[cur],  bh[nt]);
                    MMA16(acc[mt][nt], ah[cur],  bmr[nt]);
                    MMA16(acc[mt][nt], am_[cur], bh[nt]);
                }
            }
        }
        __syncthreads();
    }
    #undef ISSUE

    // epilogue
    #pragma unroll
    for (int mt = 0; mt < 4; mt++) {
        #pragma unroll
        for (int nt = 0; nt < 4; nt++) {
            int col = bn + wn + nt * 8 + 2 * t;
            float b0 = __ldg(&bias[col]);
            float b1 = __ldg(&bias[col + 1]);
            float* p0 = C + (size_t)(bm + wm + mt * 16 + g) * N + col;
            float2 o0 = make_float2(acc[mt][nt][0] + b0, acc[mt][nt][1] + b1);
            float2 o1 = make_float2(acc[mt][nt][2] + b0, acc[mt][nt][3] + b1);
            *(float2*)p0 = o0;
            *(float2*)(p0 + 8 * N) = o1;
        }
    }
}

// ---------------- FFT attention (twiddle table, writes 2x bf16) ----------------
__device__ __forceinline__ void fft1024_stages(float2* s, const float2* Tw, int tid, bool inv) {
    #pragma unroll
    for (int stage = 0; stage < 10; ++stage) {
        const int half = 1 << stage;
        #pragma unroll
        for (int r = 0; r < 2; ++r) {
            int b = tid + (r << 8);
            int pos = b & (half - 1);
            int i0 = ((b >> stage) << (stage + 1)) + pos;
            int i1 = i0 + half;
            float2 w = Tw[pos << (9 - stage)];
            float cs = w.x;
            float sn = inv ? -w.y : w.y;
            float2 x1 = s[i1];
            float2 t = make_float2(x1.x * cs - x1.y * sn, x1.x * sn + x1.y * cs);
            float2 x0 = s[i0];
            s[i0] = make_float2(x0.x + t.x, x0.y + t.y);
            s[i1] = make_float2(x0.x - t.x, x0.y - t.y);
        }
        __syncthreads();
    }
}

__global__ __launch_bounds__(256) void fft_attn_kernel(
    const float* __restrict__ Q, const float* __restrict__ Kx,
    const float* __restrict__ V,
    bf16* __restrict__ Oh, bf16* __restrict__ Om)
{
    __shared__ float2 Z[1024];
    __shared__ float2 Aw[1024];
    __shared__ float2 Tw[512];
    const int row = blockIdx.x;
    const int tid = threadIdx.x;
    const float* qr = Q  + (size_t)row * Pd;
    const float* kr = Kx + (size_t)row * Pd;
    const float* vr = V  + (size_t)row * Pd;

    for (int j = tid; j < 512; j += 256) {
        float sn, cs;
        __sincosf(-3.14159265358979323846f * (float)j / 512.0f, &sn, &cs);
        Tw[j] = make_float2(cs, sn);
    }

    for (int i = tid; i < 1024; i += 256) {
        int rdx = __brev((unsigned)i) >> 22;
        Z[rdx] = make_float2(qr[i], kr[i]);
    }
    __syncthreads();
    fft1024_stages(Z, Tw, tid, false);

    const float inv_scale = 1.0f / 32.0f;
    for (int i = tid; i < 1024; i += 256) {
        float2 zj = Z[i];
        float2 zn = Z[(1024 - i) & 1023];
        float Qx = 0.5f * (zj.x + zn.x);
        float Qy = 0.5f * (zj.y - zn.y);
        float Kxr = 0.5f * (zj.y + zn.y);
        float Kyr = -0.5f * (zj.x - zn.x);
        float Ax = Kxr * Qx + Kyr * Qy;
        float Ay = Kyr * Qx - Kxr * Qy;
        Aw[i] = make_float2(Ax * inv_scale, Ay * inv_scale);
    }
    __syncthreads();

    for (int i = tid; i < 1024; i += 256) {
        int rdx = __brev((unsigned)i) >> 22;
        Z[rdx] = make_float2(vr[i], 0.0f);
    }
    __syncthreads();
    fft1024_stages(Z, Tw, tid, false);

    for (int i = tid; i < 1024; i += 256) {
        float2 vf = Z[i], a = Aw[i];
        Aw[i] = make_float2(vf.x * a.x - vf.y * a.y, vf.x * a.y + vf.y * a.x);
    }
    __syncthreads();

    for (int i = tid; i < 1024; i += 256) {
        int rdx = __brev((unsigned)i) >> 22;
        Z[rdx] = Aw[i];
    }
    __syncthreads();
    fft1024_stages(Z, Tw, tid, true);

    bf16* oh = Oh + (size_t)row * Pd;
    bf16* om = Om + (size_t)row * Pd;
    const float invN = 1.0f / 1024.0f;
    for (int i = tid; i < 1024; i += 256) {
        float s = Z[i].x * invN;
        bf16 sh, sm_;
        split2(s, sh, sm_);
        oh[i] = sh; om[i] = sm_;
    }
}

// ---------------- launch ----------------
extern "C" void kernel_launch(void* const* d_in, const int* in_sizes, int n_in,
                              void* d_out, int out_size) {
    (void)in_sizes; (void)n_in; (void)out_size;
    const float* x      = (const float*)d_in[0];
    const float* conv_w = (const float*)d_in[1];
    const float* conv_b = (const float*)d_in[2];
    const float* wq     = (const float*)d_in[3];
    const float* bq     = (const float*)d_in[4];
    const float* wk     = (const float*)d_in[5];
    const float* bk     = (const float*)d_in[6];
    const float* wv     = (const float*)d_in[7];
    const float* bv     = (const float*)d_in[8];
    const float* wo     = (const float*)d_in[9];
    const float* bo     = (const float*)d_in[10];
    float* out = (float*)d_out;

    float *xb, *qkv, *bqkv, *wavg, *bavg;
    bf16 *ch, *cm, *ph, *pm;
    bf16 *wqkvh, *wqkvm, *woh, *wom;
    cudaGetSymbolAddress((void**)&xb,    g_x);
    cudaGetSymbolAddress((void**)&ch,    g_ch);
    cudaGetSymbolAddress((void**)&cm,    g_cm);
    cudaGetSymbolAddress((void**)&qkv,   g_qkv);
    cudaGetSymbolAddress((void**)&ph,    g_ph);
    cudaGetSymbolAddress((void**)&pm,    g_pm);
    cudaGetSymbolAddress((void**)&wqkvh, g_wqkvh);
    cudaGetSymbolAddress((void**)&wqkvm, g_wqkvm);
    cudaGetSymbolAddress((void**)&woh,   g_woh);
    cudaGetSymbolAddress((void**)&wom,   g_wom);
    cudaGetSymbolAddress((void**)&bqkv,  g_bqkv);
    cudaGetSymbolAddress((void**)&wavg,  g_wavg);
    cudaGetSymbolAddress((void**)&bavg,  g_bavg);

    cudaFuncSetAttribute(gemm_mma_kernel,
                         cudaFuncAttributeMaxDynamicSharedMemorySize, GEMM_SMEM);

    const size_t LPW = (size_t)Ld * Pd * Wd;   // 4M elements

    avg_conv_kernel<<<1, 64>>>(conv_w, conv_b, wavg, bavg);

    split2_kernel<<<1024, 256>>>(wq, wqkvh,           wqkvm,           (int)(LPW / 8));
    split2_kernel<<<1024, 256>>>(wk, wqkvh + LPW,     wqkvm + LPW,     (int)(LPW / 8));
    split2_kernel<<<1024, 256>>>(wv, wqkvh + 2 * LPW, wqkvm + 2 * LPW, (int)(LPW / 8));
    split2_kernel<<<1024, 256>>>(wo, woh,             wom,             (int)(LPW / 8));

    cudaMemcpyAsync(bqkv,               bq, Ld * Pd * 4, cudaMemcpyDeviceToDevice);
    cudaMemcpyAsync(bqkv + Ld * Pd,     bk, Ld * Pd * 4, cudaMemcpyDeviceToDevice);
    cudaMemcpyAsync(bqkv + 2 * Ld * Pd, bv, Ld * Pd * 4, cudaMemcpyDeviceToDevice);

    const size_t RP = (size_t)ROWS * Pd;

    for (int l = 0; l < Ld; l++) {
        const float* xin = (l == 0) ? x : xb;
        float* xout = (l == Ld - 1) ? out : xb;

        conv_row_kernel<<<ROWS, 256>>>(xin, ch, cm, wavg + l * Kc, bavg + l);

        dim3 gq(Pd / 128, ROWS / 128, 3);     // (8, 32, 3)
        gemm_mma_kernel<<<gq, 256, GEMM_SMEM>>>(
            ch, cm,
            wqkvh + (size_t)l * Pd * Wd, wqkvm + (size_t)l * Pd * Wd,
            bqkv + (size_t)l * Pd, qkv,
            Wd, Pd, LPW, (size_t)Ld * Pd, RP);

        fft_attn_kernel<<<ROWS, 256>>>(qkv, qkv + RP, qkv + 2 * RP, ph, pm);

        dim3 go(Wd / 128, ROWS / 128, 1);     // (16, 32, 1)
        gemm_mma_kernel<<<go, 256, GEMM_SMEM>>>(
            ph, pm,
            woh + (size_t)l * Wd * Pd, wom + (size_t)l * Wd * Pd,
            bo + (size_t)l * Wd, xout,
            Pd, Wd, 0, 0, 0);
    }
}

// round 11
// speedup vs baseline: 1.3584x; 1.2583x over previous
#include <cuda_runtime.h>
#include <cuda_fp16.h>
#include <cstdint>

#define BSZ 32
#define CNT 128
#define Wd  2048
#define Pd  1024
#define Ed  8
#define Kc  25
#define Ld  2
#define ROWS (BSZ*CNT)   // 4096

// ---------------- scratch ----------------
__device__ float  g_x[ROWS*Wd];
__device__ __half g_ch[ROWS*Wd];            // conv out, fp16 h/m planes
__device__ __half g_cm[ROWS*Wd];
__device__ float  g_qkv[3*ROWS*Pd];
__device__ __half g_ph[ROWS*Pd];
__device__ __half g_pm[ROWS*Pd];
__device__ __half g_wqkv[3*Ld*Pd*Wd];       // fp16 single-plane weights
__device__ __half g_wo[Ld*Wd*Pd];
__device__ float  g_bqkv[3*Ld*Pd];
__device__ float  g_wavg[Ld*Kc];
__device__ float  g_bavg[Ld];

// ---------------- helpers ----------------
__device__ __forceinline__ uint32_t smem_u32(const void* p) {
    uint32_t a;
    asm("{ .reg .u64 t; cvta.to.shared.u64 t, %1; cvt.u32.u64 %0, t; }" : "=r"(a) : "l"(p));
    return a;
}
__device__ __forceinline__ void cp16(uint32_t dst, const void* src) {
    asm volatile("cp.async.cg.shared.global [%0], [%1], 16;" :: "r"(dst), "l"(src));
}
__device__ __forceinline__ void split2h(float x, __half& h, __half& m) {
    h = __float2half(x);
    m = __float2half(x - __half2float(h));
}
__device__ __forceinline__ uint32_t pack2h(__half a, __half b) {
    return (uint32_t)__half_as_ushort(a) | ((uint32_t)__half_as_ushort(b) << 16);
}

// ---------------- weight convert fp32 -> fp16 ----------------
__global__ void cvt16_kernel(const float* __restrict__ src, __half* __restrict__ dst, int n8) {
    int i = blockIdx.x * blockDim.x + threadIdx.x;
    int stride = gridDim.x * blockDim.x;
    for (; i < n8; i += stride) {
        float4 v0 = ((const float4*)src)[2 * i];
        float4 v1 = ((const float4*)src)[2 * i + 1];
        uint4 u;
        u.x = pack2h(__float2half(v0.x), __float2half(v0.y));
        u.y = pack2h(__float2half(v0.z), __float2half(v0.w));
        u.z = pack2h(__float2half(v1.x), __float2half(v1.y));
        u.w = pack2h(__float2half(v1.z), __float2half(v1.w));
        ((uint4*)dst)[i] = u;
    }
}

// ---------------- avg conv weights ----------------
__global__ void avg_conv_kernel(const float* __restrict__ cw, const float* __restrict__ cb,
                                float* __restrict__ wavg, float* __restrict__ bavg) {
    int idx = threadIdx.x;
    if (idx < Ld * Kc) {
        int l = idx / Kc, kk = idx % Kc;
        float s = 0.f;
        #pragma unroll
        for (int e = 0; e < Ed; e++) s += cw[(l * Ed + e) * Kc + kk];
        wavg[idx] = s * (1.0f / Ed);
    }
    if (idx < Ld) {
        float s = 0.f;
        #pragma unroll
        for (int e = 0; e < Ed; e++) s += cb[idx * Ed + e];
        bavg[idx] = s * (1.0f / Ed);
    }
}

// ---------------- 1D conv, writes fp16 h/m ----------------
__global__ __launch_bounds__(256) void conv_row_kernel(
    const float* __restrict__ X, __half* __restrict__ Yh, __half* __restrict__ Ym,
    const float* __restrict__ wavg, const float* __restrict__ bavg)
{
    __shared__ float sx[Wd + Kc - 1];
    __shared__ float wsh[Kc];
    const int row = blockIdx.x;
    const int tid = threadIdx.x;
    const float* xr = X + (size_t)row * Wd;

    for (int i = tid; i < Wd + Kc - 1; i += 256) {
        int src = i - (Kc / 2);
        sx[i] = (src >= 0 && src < Wd) ? xr[src] : 0.0f;
    }
    if (tid < Kc) wsh[tid] = wavg[tid];
    __syncthreads();

    const float b = bavg[0];
    __half* yh = Yh + (size_t)row * Wd;
    __half* ym = Ym + (size_t)row * Wd;
    for (int h = tid; h < Wd; h += 256) {
        float s = b;
        #pragma unroll
        for (int k = 0; k < Kc; k++) s += sx[h + k] * wsh[k];
        __half sh, sm_;
        split2h(s, sh, sm_);
        yh[h] = sh; ym[h] = sm_;
    }
}

// ---------------- fp16x2 mma.sync GEMM: C = (Ah+Am)*W^T + bias ----------------
#define MMA16(cc, aa, bb) \
    asm volatile("mma.sync.aligned.m16n8k16.row.col.f32.f16.f16.f32 " \
        "{%0,%1,%2,%3},{%4,%5,%6,%7},{%8,%9},{%0,%1,%2,%3};" \
        : "+f"((cc)[0]), "+f"((cc)[1]), "+f"((cc)[2]), "+f"((cc)[3]) \
        : "r"((aa)[0]), "r"((aa)[1]), "r"((aa)[2]), "r"((aa)[3]), \
          "r"((bb)[0]), "r"((bb)[1]))

#define LDMX4(r0, r1, r2, r3, a) \
    asm volatile("ldmatrix.sync.aligned.m8n8.x4.shared.b16 {%0,%1,%2,%3}, [%4];" \
        : "=r"(r0), "=r"(r1), "=r"(r2), "=r"(r3) : "r"(a))

#define BK 32
#define TILE_W 2048            // 128 rows x 16 words (32 fp16), swizzled
#define STAGE_W (3*TILE_W)     // Ah, Am, W = 6144 words = 24KB
#define NSTAGE 3
#define GEMM_SMEM (NSTAGE*STAGE_W*4)   // 73728 bytes

__global__ __launch_bounds__(256, 2) void gemm_mma_kernel(
    const __half* __restrict__ Ah, const __half* __restrict__ Am,
    const __half* __restrict__ Bw,
    const float* __restrict__ bias, float* __restrict__ C,
    int Kd, int N, size_t szB, size_t szBias, size_t szC)
{
    extern __shared__ uint32_t sm[];
    const uint32_t sbase = smem_u32(sm);
    const int z = blockIdx.z;
    Bw   += (size_t)z * szB;
    bias += (size_t)z * szBias;
    C    += (size_t)z * szC;

    const int tid = threadIdx.x;
    const int wid = tid >> 5, lane = tid & 31;
    const int g = lane >> 2, t = lane & 3;
    const int wm = (wid >> 2) * 64;       // 2 m-warp groups
    const int wn = (wid & 3) * 32;        // 4 n-warp groups
    const int bm = blockIdx.y * 128, bn = blockIdx.x * 128;
    const int stA = wid & 1;              // per-warp substep stagger

    // ---- ldmatrix per-lane byte offsets (bases; +1024B per 16-row step) ----
    const int lr = lane & 7;
    const int ls = lane >> 3;   // 0..3
    uint32_t Abase[2], Bbase[2];
    #pragma unroll
    for (int st = 0; st < 2; st++) {
        int arow = wm + lr + (ls & 1) * 8;
        int awc2 = st * 2 + (ls >> 1);
        Abase[st] = (uint32_t)(arow * 16 + ((awc2 ^ ((arow >> 1) & 3)) << 2)) * 4;
        int brow = wn + (ls >> 1) * 8 + lr;
        int bwc2 = st * 2 + (ls & 1);
        Bbase[st] = (uint32_t)(brow * 16 + ((bwc2 ^ ((brow >> 1) & 3)) << 2)) * 4;
    }

    // cp.async mapping: 512 16B-groups per tile; thread covers tid, tid+256
    const int r0 = tid >> 2, c0 = tid & 3;
    const int r1 = r0 + 64;
    const uint32_t d0 = (uint32_t)(r0 * 16 + ((c0 ^ ((r0 >> 1) & 3)) << 2)) * 4;
    const uint32_t d1 = (uint32_t)(r1 * 16 + ((c0 ^ ((r1 >> 1) & 3)) << 2)) * 4;

    const __half* a0h = Ah + (size_t)(bm + r0) * Kd + c0 * 8;
    const __half* a0m = Am + (size_t)(bm + r0) * Kd + c0 * 8;
    const __half* a1h = Ah + (size_t)(bm + r1) * Kd + c0 * 8;
    const __half* a1m = Am + (size_t)(bm + r1) * Kd + c0 * 8;
    const __half* b0w = Bw + (size_t)(bn + r0) * Kd + c0 * 8;
    const __half* b1w = Bw + (size_t)(bn + r1) * Kd + c0 * 8;

    float acc[4][4][4];
    #pragma unroll
    for (int mt = 0; mt < 4; mt++)
        #pragma unroll
        for (int nt = 0; nt < 4; nt++)
            #pragma unroll
            for (int e = 0; e < 4; e++) acc[mt][nt][e] = 0.0f;

    const int NC = Kd / BK;

    #define ISSUE(s, kpos) do { \
        uint32_t _sb = sbase + (uint32_t)(s) * (STAGE_W * 4); \
        cp16(_sb + d0,                   a0h + (kpos)); \
        cp16(_sb + d1,                   a1h + (kpos)); \
        cp16(_sb + TILE_W * 4 + d0,      a0m + (kpos)); \
        cp16(_sb + TILE_W * 4 + d1,      a1m + (kpos)); \
        cp16(_sb + 2 * TILE_W * 4 + d0,  b0w + (kpos)); \
        cp16(_sb + 2 * TILE_W * 4 + d1,  b1w + (kpos)); \
        asm volatile("cp.async.commit_group;" ::: "memory"); \
    } while (0)

    ISSUE(0, 0);
    ISSUE(1, BK);

    for (int i = 0; i < NC; i++) {
        if (i + 1 < NC) asm volatile("cp.async.wait_group 1;" ::: "memory");
        else            asm volatile("cp.async.wait_group 0;" ::: "memory");
        __syncthreads();
        if (i + 2 < NC) {
            int s = i + 2; s = s - (s / 3) * 3;
            ISSUE(s, (i + 2) * BK);
        }

        int bsel = i - (i / 3) * 3;
        const uint32_t sAh = sbase + (uint32_t)bsel * (STAGE_W * 4);
        const uint32_t sAm = sAh + TILE_W * 4;
        const uint32_t sBw = sAm + TILE_W * 4;

        #pragma unroll
        for (int s = 0; s < 2; s++) {
            const int st = s ^ stA;                 // staggered substep order
            const uint32_t ab = Abase[st];
            const uint32_t bb = Bbase[st];

            uint32_t bw[4][2];
            LDMX4(bw[0][0], bw[0][1], bw[1][0], bw[1][1], sBw + bb);
            LDMX4(bw[2][0], bw[2][1], bw[3][0], bw[3][1], sBw + bb + 1024);

            // one-ahead A pipeline
            uint32_t ah[2][4], am_[2][4];
            LDMX4(ah[0][0], ah[0][1], ah[0][2], ah[0][3], sAh + ab);
            LDMX4(am_[0][0], am_[0][1], am_[0][2], am_[0][3], sAm + ab);
            #pragma unroll
            for (int mt = 0; mt < 4; mt++) {
                const int cur = mt & 1, nxt = cur ^ 1;
                if (mt < 3) {
                    uint32_t ao = ab + (uint32_t)(mt + 1) * 1024;
                    LDMX4(ah[nxt][0], ah[nxt][1], ah[nxt][2], ah[nxt][3], sAh + ao);
                    LDMX4(am_[nxt][0], am_[nxt][1], am_[nxt][2], am_[nxt][3], sAm + ao);
                }
                #pragma unroll
                for (int nt = 0; nt < 4; nt++) {
                    MMA16(acc[mt][nt], ah[cur],  bw[nt]);
                    MMA16(acc[mt][nt], am_[cur], bw[nt]);
                }
            }
        }
        __syncthreads();
    }
    #undef ISSUE

    // epilogue
    #pragma unroll
    for (int mt = 0; mt < 4; mt++) {
        #pragma unroll
        for (int nt = 0; nt < 4; nt++) {
            int col = bn + wn + nt * 8 + 2 * t;
            float b0 = __ldg(&bias[col]);
            float b1 = __ldg(&bias[col + 1]);
            float* p0 = C + (size_t)(bm + wm + mt * 16 + g) * N + col;
            float2 o0 = make_float2(acc[mt][nt][0] + b0, acc[mt][nt][1] + b1);
            float2 o1 = make_float2(acc[mt][nt][2] + b0, acc[mt][nt][3] + b1);
            *(float2*)p0 = o0;
            *(float2*)(p0 + 8 * N) = o1;
        }
    }
}

// ---------------- FFT attention (twiddle table, writes fp16 h/m) ----------------
__device__ __forceinline__ void fft1024_stages(float2* s, const float2* Tw, int tid, bool inv) {
    #pragma unroll
    for (int stage = 0; stage < 10; ++stage) {
        const int half = 1 << stage;
        #pragma unroll
        for (int r = 0; r < 2; ++r) {
            int b = tid + (r << 8);
            int pos = b & (half - 1);
            int i0 = ((b >> stage) << (stage + 1)) + pos;
            int i1 = i0 + half;
            float2 w = Tw[pos << (9 - stage)];
            float cs = w.x;
            float sn = inv ? -w.y : w.y;
            float2 x1 = s[i1];
            float2 t = make_float2(x1.x * cs - x1.y * sn, x1.x * sn + x1.y * cs);
            float2 x0 = s[i0];
            s[i0] = make_float2(x0.x + t.x, x0.y + t.y);
            s[i1] = make_float2(x0.x - t.x, x0.y - t.y);
        }
        __syncthreads();
    }
}

__global__ __launch_bounds__(256) void fft_attn_kernel(
    const float* __restrict__ Q, const float* __restrict__ Kx,
    const float* __restrict__ V,
    __half* __restrict__ Oh, __half* __restrict__ Om)
{
    __shared__ float2 Z[1024];
    __shared__ float2 Aw[1024];
    __shared__ float2 Tw[512];
    const int row = blockIdx.x;
    const int tid = threadIdx.x;
    const float* qr = Q  + (size_t)row * Pd;
    const float* kr = Kx + (size_t)row * Pd;
    const float* vr = V  + (size_t)row * Pd;

    for (int j = tid; j < 512; j += 256) {
        float sn, cs;
        __sincosf(-3.14159265358979323846f * (float)j / 512.0f, &sn, &cs);
        Tw[j] = make_float2(cs, sn);
    }

    for (int i = tid; i < 1024; i += 256) {
        int rdx = __brev((unsigned)i) >> 22;
        Z[rdx] = make_float2(qr[i], kr[i]);
    }
    __syncthreads();
    fft1024_stages(Z, Tw, tid, false);

    const float inv_scale = 1.0f / 32.0f;
    for (int i = tid; i < 1024; i += 256) {
        float2 zj = Z[i];
        float2 zn = Z[(1024 - i) & 1023];
        float Qx = 0.5f * (zj.x + zn.x);
        float Qy = 0.5f * (zj.y - zn.y);
        float Kxr = 0.5f * (zj.y + zn.y);
        float Kyr = -0.5f * (zj.x - zn.x);
        float Ax = Kxr * Qx + Kyr * Qy;
        float Ay = Kyr * Qx - Kxr * Qy;
        Aw[i] = make_float2(Ax * inv_scale, Ay * inv_scale);
    }
    __syncthreads();

    for (int i = tid; i < 1024; i += 256) {
        int rdx = __brev((unsigned)i) >> 22;
        Z[rdx] = make_float2(vr[i], 0.0f);
    }
    __syncthreads();
    fft1024_stages(Z, Tw, tid, false);

    for (int i = tid; i < 1024; i += 256) {
        float2 vf = Z[i], a = Aw[i];
        Aw[i] = make_float2(vf.x * a.x - vf.y * a.y, vf.x * a.y + vf.y * a.x);
    }
    __syncthreads();

    for (int i = tid; i < 1024; i += 256) {
        int rdx = __brev((unsigned)i) >> 22;
        Z[rdx] = Aw[i];
    }
    __syncthreads();
    fft1024_stages(Z, Tw, tid, true);

    __half* oh = Oh + (size_t)row * Pd;
    __half* om = Om + (size_t)row * Pd;
    const float invN = 1.0f / 1024.0f;
    for (int i = tid; i < 1024; i += 256) {
        float s = Z[i].x * invN;
        __half sh, sm_;
        split2h(s, sh, sm_);
        oh[i] = sh; om[i] = sm_;
    }
}

// ---------------- launch ----------------
extern "C" void kernel_launch(void* const* d_in, const int* in_sizes, int n_in,
                              void* d_out, int out_size) {
    (void)in_sizes; (void)n_in; (void)out_size;
    const float* x      = (const float*)d_in[0];
    const float* conv_w = (const float*)d_in[1];
    const float* conv_b = (const float*)d_in[2];
    const float* wq     = (const float*)d_in[3];
    const float* bq     = (const float*)d_in[4];
    const float* wk     = (const float*)d_in[5];
    const float* bk     = (const float*)d_in[6];
    const float* wv     = (const float*)d_in[7];
    const float* bv     = (const float*)d_in[8];
    const float* wo     = (const float*)d_in[9];
    const float* bo     = (const float*)d_in[10];
    float* out = (float*)d_out;

    float *xb, *qkv, *bqkv, *wavg, *bavg;
    __half *ch, *cm, *ph, *pm, *wqkvh, *woh;
    cudaGetSymbolAddress((void**)&xb,    g_x);
    cudaGetSymbolAddress((void**)&ch,    g_ch);
    cudaGetSymbolAddress((void**)&cm,    g_cm);
    cudaGetSymbolAddress((void**)&qkv,   g_qkv);
    cudaGetSymbolAddress((void**)&ph,    g_ph);
    cudaGetSymbolAddress((void**)&pm,    g_pm);
    cudaGetSymbolAddress((void**)&wqkvh, g_wqkv);
    cudaGetSymbolAddress((void**)&woh,   g_wo);
    cudaGetSymbolAddress((void**)&bqkv,  g_bqkv);
    cudaGetSymbolAddress((void**)&wavg,  g_wavg);
    cudaGetSymbolAddress((void**)&bavg,  g_bavg);

    cudaFuncSetAttribute(gemm_mma_kernel,
                         cudaFuncAttributeMaxDynamicSharedMemorySize, GEMM_SMEM);

    const size_t LPW = (size_t)Ld * Pd * Wd;   // 4M elements

    avg_conv_kernel<<<1, 64>>>(conv_w, conv_b, wavg, bavg);

    cvt16_kernel<<<1024, 256>>>(wq, wqkvh,           (int)(LPW / 8));
    cvt16_kernel<<<1024, 256>>>(wk, wqkvh + LPW,     (int)(LPW / 8));
    cvt16_kernel<<<1024, 256>>>(wv, wqkvh + 2 * LPW, (int)(LPW / 8));
    cvt16_kernel<<<1024, 256>>>(wo, woh,             (int)(LPW / 8));

    cudaMemcpyAsync(bqkv,               bq, Ld * Pd * 4, cudaMemcpyDeviceToDevice);
    cudaMemcpyAsync(bqkv + Ld * Pd,     bk, Ld * Pd * 4, cudaMemcpyDeviceToDevice);
    cudaMemcpyAsync(bqkv + 2 * Ld * Pd, bv, Ld * Pd * 4, cudaMemcpyDeviceToDevice);

    const size_t RP = (size_t)ROWS * Pd;

    for (int l = 0; l < Ld; l++) {
        const float* xin = (l == 0) ? x : xb;
        float* xout = (l == Ld - 1) ? out : xb;

        conv_row_kernel<<<ROWS, 256>>>(xin, ch, cm, wavg + l * Kc, bavg + l);

        dim3 gq(Pd / 128, ROWS / 128, 3);     // (8, 32, 3)
        gemm_mma_kernel<<<gq, 256, GEMM_SMEM>>>(
            ch, cm,
            wqkvh + (size_t)l * Pd * Wd,
            bqkv + (size_t)l * Pd, qkv,
            Wd, Pd, LPW, (size_t)Ld * Pd, RP);

        fft_attn_kernel<<<ROWS, 256>>>(qkv, qkv + RP, qkv + 2 * RP, ph, pm);

        dim3 go(Wd / 128, ROWS / 128, 1);     // (16, 32, 1)
        gemm_mma_kernel<<<go, 256, GEMM_SMEM>>>(
            ph, pm,
            woh + (size_t)l * Wd * Pd,
            bo + (size_t)l * Wd, xout,
            Pd, Wd, 0, 0, 0);
    }
}

// round 12
// speedup vs baseline: 1.5253x; 1.1229x over previous
#include <cuda_runtime.h>
#include <cuda_fp16.h>
#include <cstdint>

#define BSZ 32
#define CNT 128
#define Wd  2048
#define Pd  1024
#define Ed  8
#define Kc  25
#define Ld  2
#define ROWS (BSZ*CNT)   // 4096

// ---------------- scratch ----------------
__device__ float  g_x[ROWS*Wd];
__device__ __half g_ch[ROWS*Wd];            // conv out, fp16 h/m planes
__device__ __half g_cm[ROWS*Wd];
__device__ float  g_qkv[3*ROWS*Pd];
__device__ __half g_ph[ROWS*Pd];
__device__ __half g_pm[ROWS*Pd];
__device__ __half g_wqkv[3*Ld*Pd*Wd];       // fp16 single-plane weights
__device__ __half g_wo[Ld*Wd*Pd];
__device__ float  g_bqkv[3*Ld*Pd];
__device__ float  g_wavg[Ld*Kc];
__device__ float  g_bavg[Ld];

// ---------------- helpers ----------------
__device__ __forceinline__ uint32_t smem_u32(const void* p) {
    uint32_t a;
    asm("{ .reg .u64 t; cvta.to.shared.u64 t, %1; cvt.u32.u64 %0, t; }" : "=r"(a) : "l"(p));
    return a;
}
__device__ __forceinline__ void cp16(uint32_t dst, const void* src) {
    asm volatile("cp.async.cg.shared.global [%0], [%1], 16;" :: "r"(dst), "l"(src));
}
__device__ __forceinline__ void split2h(float x, __half& h, __half& m) {
    h = __float2half(x);
    m = __float2half(x - __half2float(h));
}
__device__ __forceinline__ uint32_t pack2h(__half a, __half b) {
    return (uint32_t)__half_as_ushort(a) | ((uint32_t)__half_as_ushort(b) << 16);
}
__device__ __forceinline__ float2 cmulf(float2 a, float2 b) {
    return make_float2(a.x * b.x - a.y * b.y, a.x * b.y + a.y * b.x);
}

// ---------------- weight convert fp32 -> fp16 ----------------
__global__ void cvt16_kernel(const float* __restrict__ src, __half* __restrict__ dst, int n8) {
    int i = blockIdx.x * blockDim.x + threadIdx.x;
    int stride = gridDim.x * blockDim.x;
    for (; i < n8; i += stride) {
        float4 v0 = ((const float4*)src)[2 * i];
        float4 v1 = ((const float4*)src)[2 * i + 1];
        uint4 u;
        u.x = pack2h(__float2half(v0.x), __float2half(v0.y));
        u.y = pack2h(__float2half(v0.z), __float2half(v0.w));
        u.z = pack2h(__float2half(v1.x), __float2half(v1.y));
        u.w = pack2h(__float2half(v1.z), __float2half(v1.w));
        ((uint4*)dst)[i] = u;
    }
}

// ---------------- avg conv weights ----------------
__global__ void avg_conv_kernel(const float* __restrict__ cw, const float* __restrict__ cb,
                                float* __restrict__ wavg, float* __restrict__ bavg) {
    int idx = threadIdx.x;
    if (idx < Ld * Kc) {
        int l = idx / Kc, kk = idx % Kc;
        float s = 0.f;
        #pragma unroll
        for (int e = 0; e < Ed; e++) s += cw[(l * Ed + e) * Kc + kk];
        wavg[idx] = s * (1.0f / Ed);
    }
    if (idx < Ld) {
        float s = 0.f;
        #pragma unroll
        for (int e = 0; e < Ed; e++) s += cb[idx * Ed + e];
        bavg[idx] = s * (1.0f / Ed);
    }
}

// ---------------- 1D conv, writes fp16 h/m ----------------
__global__ __launch_bounds__(256) void conv_row_kernel(
    const float* __restrict__ X, __half* __restrict__ Yh, __half* __restrict__ Ym,
    const float* __restrict__ wavg, const float* __restrict__ bavg)
{
    __shared__ float sx[Wd + Kc - 1];
    __shared__ float wsh[Kc];
    const int row = blockIdx.x;
    const int tid = threadIdx.x;
    const float* xr = X + (size_t)row * Wd;

    for (int i = tid; i < Wd + Kc - 1; i += 256) {
        int src = i - (Kc / 2);
        sx[i] = (src >= 0 && src < Wd) ? xr[src] : 0.0f;
    }
    if (tid < Kc) wsh[tid] = wavg[tid];
    __syncthreads();

    const float b = bavg[0];
    __half* yh = Yh + (size_t)row * Wd;
    __half* ym = Ym + (size_t)row * Wd;
    for (int h = tid; h < Wd; h += 256) {
        float s = b;
        #pragma unroll
        for (int k = 0; k < Kc; k++) s += sx[h + k] * wsh[k];
        __half sh, sm_;
        split2h(s, sh, sm_);
        yh[h] = sh; ym[h] = sm_;
    }
}

// ---------------- fp16x2 mma.sync GEMM, 32x64 warp tile ----------------
#define MMA16(cc, aa, bb) \
    asm volatile("mma.sync.aligned.m16n8k16.row.col.f32.f16.f16.f32 " \
        "{%0,%1,%2,%3},{%4,%5,%6,%7},{%8,%9},{%0,%1,%2,%3};" \
        : "+f"((cc)[0]), "+f"((cc)[1]), "+f"((cc)[2]), "+f"((cc)[3]) \
        : "r"((aa)[0]), "r"((aa)[1]), "r"((aa)[2]), "r"((aa)[3]), \
          "r"((bb)[0]), "r"((bb)[1]))

#define LDMX4(r0, r1, r2, r3, a) \
    asm volatile("ldmatrix.sync.aligned.m8n8.x4.shared.b16 {%0,%1,%2,%3}, [%4];" \
        : "=r"(r0), "=r"(r1), "=r"(r2), "=r"(r3) : "r"(a))

#define BK 32
#define TILE_W 2048            // 128 rows x 16 words (32 fp16), swizzled
#define STAGE_W (3*TILE_W)     // Ah, Am, W = 6144 words = 24KB
#define NSTAGE 3
#define GEMM_SMEM (NSTAGE*STAGE_W*4)   // 73728 bytes

__global__ __launch_bounds__(256, 2) void gemm_mma_kernel(
    const __half* __restrict__ Ah, const __half* __restrict__ Am,
    const __half* __restrict__ Bw,
    const float* __restrict__ bias, float* __restrict__ C,
    int Kd, int N, size_t szB, size_t szBias, size_t szC)
{
    extern __shared__ uint32_t sm[];
    const uint32_t sbase = smem_u32(sm);
    const int z = blockIdx.z;
    Bw   += (size_t)z * szB;
    bias += (size_t)z * szBias;
    C    += (size_t)z * szC;

    const int tid = threadIdx.x;
    const int wid = tid >> 5, lane = tid & 31;
    const int g = lane >> 2, t = lane & 3;
    const int wm = (wid >> 1) * 32;       // 4 m-warp groups x 32 rows
    const int wn = (wid & 1) * 64;        // 2 n-warp groups x 64 cols
    const int bm = blockIdx.y * 128, bn = blockIdx.x * 128;
    const int stA = wid & 1;              // per-warp substep stagger

    // ---- ldmatrix per-lane byte offsets (bases; +1024B per 16-row step) ----
    const int lr = lane & 7;
    const int ls = lane >> 3;   // 0..3
    uint32_t Abase[2], Bbase[2];
    #pragma unroll
    for (int st = 0; st < 2; st++) {
        int arow = wm + lr + (ls & 1) * 8;
        int awc2 = st * 2 + (ls >> 1);
        Abase[st] = (uint32_t)(arow * 16 + ((awc2 ^ ((arow >> 1) & 3)) << 2)) * 4;
        int brow = wn + (ls >> 1) * 8 + lr;
        int bwc2 = st * 2 + (ls & 1);
        Bbase[st] = (uint32_t)(brow * 16 + ((bwc2 ^ ((brow >> 1) & 3)) << 2)) * 4;
    }

    // cp.async mapping: 512 16B-groups per tile; thread covers tid, tid+256
    const int r0 = tid >> 2, c0 = tid & 3;
    const int r1 = r0 + 64;
    const uint32_t d0 = (uint32_t)(r0 * 16 + ((c0 ^ ((r0 >> 1) & 3)) << 2)) * 4;
    const uint32_t d1 = (uint32_t)(r1 * 16 + ((c0 ^ ((r1 >> 1) & 3)) << 2)) * 4;

    const __half* a0h = Ah + (size_t)(bm + r0) * Kd + c0 * 8;
    const __half* a0m = Am + (size_t)(bm + r0) * Kd + c0 * 8;
    const __half* a1h = Ah + (size_t)(bm + r1) * Kd + c0 * 8;
    const __half* a1m = Am + (size_t)(bm + r1) * Kd + c0 * 8;
    const __half* b0w = Bw + (size_t)(bn + r0) * Kd + c0 * 8;
    const __half* b1w = Bw + (size_t)(bn + r1) * Kd + c0 * 8;

    float acc[2][8][4];
    #pragma unroll
    for (int mt = 0; mt < 2; mt++)
        #pragma unroll
        for (int nt = 0; nt < 8; nt++)
            #pragma unroll
            for (int e = 0; e < 4; e++) acc[mt][nt][e] = 0.0f;

    const int NC = Kd / BK;

    #define ISSUE(s, kpos) do { \
        uint32_t _sb = sbase + (uint32_t)(s) * (STAGE_W * 4); \
        cp16(_sb + d0,                   a0h + (kpos)); \
        cp16(_sb + d1,                   a1h + (kpos)); \
        cp16(_sb + TILE_W * 4 + d0,      a0m + (kpos)); \
        cp16(_sb + TILE_W * 4 + d1,      a1m + (kpos)); \
        cp16(_sb + 2 * TILE_W * 4 + d0,  b0w + (kpos)); \
        cp16(_sb + 2 * TILE_W * 4 + d1,  b1w + (kpos)); \
        asm volatile("cp.async.commit_group;" ::: "memory"); \
    } while (0)

    ISSUE(0, 0);
    ISSUE(1, BK);

    for (int i = 0; i < NC; i++) {
        if (i + 1 < NC) asm volatile("cp.async.wait_group 1;" ::: "memory");
        else            asm volatile("cp.async.wait_group 0;" ::: "memory");
        __syncthreads();
        if (i + 2 < NC) {
            int s = i + 2; s = s - (s / 3) * 3;
            ISSUE(s, (i + 2) * BK);
        }

        int bsel = i - (i / 3) * 3;
        const uint32_t sAh = sbase + (uint32_t)bsel * (STAGE_W * 4);
        const uint32_t sAm = sAh + TILE_W * 4;
        const uint32_t sBw = sAm + TILE_W * 4;

        #pragma unroll
        for (int s = 0; s < 2; s++) {
            const int st = s ^ stA;                 // staggered substep order
            const uint32_t ab = Abase[st];
            const uint32_t bb = Bbase[st];

            // B fragments: 8 n-tiles (4 LDMX4)
            uint32_t bw[8][2];
            LDMX4(bw[0][0], bw[0][1], bw[1][0], bw[1][1], sBw + bb);
            LDMX4(bw[2][0], bw[2][1], bw[3][0], bw[3][1], sBw + bb + 1024);
            LDMX4(bw[4][0], bw[4][1], bw[5][0], bw[5][1], sBw + bb + 2048);
            LDMX4(bw[6][0], bw[6][1], bw[7][0], bw[7][1], sBw + bb + 3072);

            #pragma unroll
            for (int mt = 0; mt < 2; mt++) {
                uint32_t ah[4], am_[4];
                uint32_t ao = ab + (uint32_t)mt * 1024;
                LDMX4(ah[0], ah[1], ah[2], ah[3], sAh + ao);
                LDMX4(am_[0], am_[1], am_[2], am_[3], sAm + ao);
                #pragma unroll
                for (int nt = 0; nt < 8; nt++) {
                    MMA16(acc[mt][nt], ah,  bw[nt]);
                    MMA16(acc[mt][nt], am_, bw[nt]);
                }
            }
        }
        __syncthreads();
    }
    #undef ISSUE

    // epilogue
    #pragma unroll
    for (int mt = 0; mt < 2; mt++) {
        #pragma unroll
        for (int nt = 0; nt < 8; nt++) {
            int col = bn + wn + nt * 8 + 2 * t;
            float b0 = __ldg(&bias[col]);
            float b1 = __ldg(&bias[col + 1]);
            float* p0 = C + (size_t)(bm + wm + mt * 16 + g) * N + col;
            float2 o0 = make_float2(acc[mt][nt][0] + b0, acc[mt][nt][1] + b1);
            float2 o1 = make_float2(acc[mt][nt][2] + b0, acc[mt][nt][3] + b1);
            *(float2*)p0 = o0;
            *(float2*)(p0 + 8 * N) = o1;
        }
    }
}

// ---------------- radix-4 FFT attention ----------------
__device__ __forceinline__ int rev4(int v) {
    return ((v & 3) << 8) | (((v >> 2) & 3) << 6) | (((v >> 4) & 3) << 4)
         | (((v >> 6) & 3) << 2) | ((v >> 8) & 3);
}

// 1024-pt radix-4 DIT; input digit-reversed (base 4), output natural.
__device__ __forceinline__ void fft1024_r4(float2* s, const float2* Tw, int tid, bool inv) {
    #pragma unroll
    for (int stage = 0; stage < 5; ++stage) {
        const int q = 1 << (2 * stage);        // 1,4,16,64,256
        const int j = tid & (q - 1);
        const int grp = tid >> (2 * stage);
        const int i0 = grp * (q << 2) + j;
        const int i1 = i0 + q, i2 = i1 + q, i3 = i2 + q;

        float2 w1 = Tw[j << (8 - 2 * stage)];
        if (inv) w1.y = -w1.y;
        float2 w2 = cmulf(w1, w1);
        float2 w3 = cmulf(w1, w2);

        float2 a = s[i0];
        float2 b = cmulf(s[i1], w1);
        float2 c = cmulf(s[i2], w2);
        float2 d = cmulf(s[i3], w3);

        float2 acp = make_float2(a.x + c.x, a.y + c.y);
        float2 acm = make_float2(a.x - c.x, a.y - c.y);
        float2 bdp = make_float2(b.x + d.x, b.y + d.y);
        float2 bdm = make_float2(b.x - d.x, b.y - d.y);
        // forward: ±(-i)·bdm ; inverse: ±(+i)·bdm
        float2 ib = inv ? make_float2(-bdm.y, bdm.x) : make_float2(bdm.y, -bdm.x);

        s[i0] = make_float2(acp.x + bdp.x, acp.y + bdp.y);
        s[i1] = make_float2(acm.x + ib.x,  acm.y + ib.y);
        s[i2] = make_float2(acp.x - bdp.x, acp.y - bdp.y);
        s[i3] = make_float2(acm.x - ib.x,  acm.y - ib.y);
        __syncthreads();
    }
}

__global__ __launch_bounds__(256) void fft_attn_kernel(
    const float* __restrict__ Q, const float* __restrict__ Kx,
    const float* __restrict__ V,
    __half* __restrict__ Oh, __half* __restrict__ Om)
{
    __shared__ float2 Z[1024];
    __shared__ float2 Aw[1024];
    __shared__ float2 Tw[256];
    const int row = blockIdx.x;
    const int tid = threadIdx.x;
    const float* qr = Q  + (size_t)row * Pd;
    const float* kr = Kx + (size_t)row * Pd;
    const float* vr = V  + (size_t)row * Pd;

    {
        float sn, cs;
        __sincosf(-6.283185307179586f * (float)tid / 1024.0f, &sn, &cs);
        Tw[tid] = make_float2(cs, sn);
    }

    #pragma unroll
    for (int u = 0; u < 4; u++) {
        int i = tid + u * 256;
        Z[rev4(i)] = make_float2(qr[i], kr[i]);
    }
    __syncthreads();
    fft1024_r4(Z, Tw, tid, false);

    const float inv_scale = 1.0f / 32.0f;
    #pragma unroll
    for (int u = 0; u < 4; u++) {
        int i = tid + u * 256;
        float2 zj = Z[i];
        float2 zn = Z[(1024 - i) & 1023];
        float Qx = 0.5f * (zj.x + zn.x);
        float Qy = 0.5f * (zj.y - zn.y);
        float Kxr = 0.5f * (zj.y + zn.y);
        float Kyr = -0.5f * (zj.x - zn.x);
        float Ax = Kxr * Qx + Kyr * Qy;
        float Ay = Kyr * Qx - Kxr * Qy;
        Aw[i] = make_float2(Ax * inv_scale, Ay * inv_scale);
    }
    __syncthreads();

    #pragma unroll
    for (int u = 0; u < 4; u++) {
        int i = tid + u * 256;
        Z[rev4(i)] = make_float2(vr[i], 0.0f);
    }
    __syncthreads();
    fft1024_r4(Z, Tw, tid, false);

    #pragma unroll
    for (int u = 0; u < 4; u++) {
        int i = tid + u * 256;
        float2 vf = Z[i], a = Aw[i];
        Aw[i] = make_float2(vf.x * a.x - vf.y * a.y, vf.x * a.y + vf.y * a.x);
    }
    __syncthreads();

    #pragma unroll
    for (int u = 0; u < 4; u++) {
        int i = tid + u * 256;
        Z[rev4(i)] = Aw[i];
    }
    __syncthreads();
    fft1024_r4(Z, Tw, tid, true);

    __half* oh = Oh + (size_t)row * Pd;
    __half* om = Om + (size_t)row * Pd;
    const float invN = 1.0f / 1024.0f;
    #pragma unroll
    for (int u = 0; u < 4; u++) {
        int i = tid + u * 256;
        float s = Z[i].x * invN;
        __half sh, sm_;
        split2h(s, sh, sm_);
        oh[i] = sh; om[i] = sm_;
    }
}

// ---------------- launch ----------------
extern "C" void kernel_launch(void* const* d_in, const int* in_sizes, int n_in,
                              void* d_out, int out_size) {
    (void)in_sizes; (void)n_in; (void)out_size;
    const float* x      = (const float*)d_in[0];
    const float* conv_w = (const float*)d_in[1];
    const float* conv_b = (const float*)d_in[2];
    const float* wq     = (const float*)d_in[3];
    const float* bq     = (const float*)d_in[4];
    const float* wk     = (const float*)d_in[5];
    const float* bk     = (const float*)d_in[6];
    const float* wv     = (const float*)d_in[7];
    const float* bv     = (const float*)d_in[8];
    const float* wo     = (const float*)d_in[9];
    const float* bo     = (const float*)d_in[10];
    float* out = (float*)d_out;

    float *xb, *qkv, *bqkv, *wavg, *bavg;
    __half *ch, *cm, *ph, *pm, *wqkvh, *woh;
    cudaGetSymbolAddress((void**)&xb,    g_x);
    cudaGetSymbolAddress((void**)&ch,    g_ch);
    cudaGetSymbolAddress((void**)&cm,    g_cm);
    cudaGetSymbolAddress((void**)&qkv,   g_qkv);
    cudaGetSymbolAddress((void**)&ph,    g_ph);
    cudaGetSymbolAddress((void**)&pm,    g_pm);
    cudaGetSymbolAddress((void**)&wqkvh, g_wqkv);
    cudaGetSymbolAddress((void**)&woh,   g_wo);
    cudaGetSymbolAddress((void**)&bqkv,  g_bqkv);
    cudaGetSymbolAddress((void**)&wavg,  g_wavg);
    cudaGetSymbolAddress((void**)&bavg,  g_bavg);

    cudaFuncSetAttribute(gemm_mma_kernel,
                         cudaFuncAttributeMaxDynamicSharedMemorySize, GEMM_SMEM);

    const size_t LPW = (size_t)Ld * Pd * Wd;   // 4M elements

    avg_conv_kernel<<<1, 64>>>(conv_w, conv_b, wavg, bavg);

    cvt16_kernel<<<1024, 256>>>(wq, wqkvh,           (int)(LPW / 8));
    cvt16_kernel<<<1024, 256>>>(wk, wqkvh + LPW,     (int)(LPW / 8));
    cvt16_kernel<<<1024, 256>>>(wv, wqkvh + 2 * LPW, (int)(LPW / 8));
    cvt16_kernel<<<1024, 256>>>(wo, woh,             (int)(LPW / 8));

    cudaMemcpyAsync(bqkv,               bq, Ld * Pd * 4, cudaMemcpyDeviceToDevice);
    cudaMemcpyAsync(bqkv + Ld * Pd,     bk, Ld * Pd * 4, cudaMemcpyDeviceToDevice);
    cudaMemcpyAsync(bqkv + 2 * Ld * Pd, bv, Ld * Pd * 4, cudaMemcpyDeviceToDevice);

    const size_t RP = (size_t)ROWS * Pd;

    for (int l = 0; l < Ld; l++) {
        const float* xin = (l == 0) ? x : xb;
        float* xout = (l == Ld - 1) ? out : xb;

        conv_row_kernel<<<ROWS, 256>>>(xin, ch, cm, wavg + l * Kc, bavg + l);

        dim3 gq(Pd / 128, ROWS / 128, 3);     // (8, 32, 3)
        gemm_mma_kernel<<<gq, 256, GEMM_SMEM>>>(
            ch, cm,
            wqkvh + (size_t)l * Pd * Wd,
            bqkv + (size_t)l * Pd, qkv,
            Wd, Pd, LPW, (size_t)Ld * Pd, RP);

        fft_attn_kernel<<<ROWS, 256>>>(qkv, qkv + RP, qkv + 2 * RP, ph, pm);

        dim3 go(Wd / 128, ROWS / 128, 1);     // (16, 32, 1)
        gemm_mma_kernel<<<go, 256, GEMM_SMEM>>>(
            ph, pm,
            woh + (size_t)l * Wd * Pd,
            bo + (size_t)l * Wd, xout,
            Pd, Wd, 0, 0, 0);
    }
}